// round 1
// baseline (speedup 1.0000x reference)
#include <cuda_runtime.h>
#include <math.h>

#define BATCH 4
#define HH 128
#define WW 128
#define HW 16384
#define NCH 64
#define C3 192
#define NHEADS 4
#define HD 16
#define NKEY 100

// ---------------- scratch (static device memory; no allocs) ----------------
__device__ float g_y1[BATCH*C3*HW];    // conv1x1 out; later reused: [0,4M)=g, [4M,8M)=o2
__device__ float g_qkv[BATCH*C3*HW];   // after depthwise 3x3: q|k|v
__device__ float g_attn[BATCH*NCH*HW]; // attention output, scattered to original channels
__device__ float g_out3[BATCH*NCH*HW]; // after proj
__device__ float g_lp[BATCH*NCH*HW];   // after reflect dw3x3
__device__ float g_S[BATCH*NCH];
__device__ float g_Gpart[BATCH*32*NCH*NCH];
__device__ int   g_idx[BATCH*NCH];

// ---------------- fused maxpool2 + conv1x1 (64 -> 192) ----------------
__global__ __launch_bounds__(128) void k_pool_qkv(const float* __restrict__ x,
                                                  const float* __restrict__ wq){
  __shared__ float ws[C3*NCH];                 // 48KB
  for (int i = threadIdx.x; i < C3*NCH; i += 128) ws[i] = wq[i];
  __syncthreads();
  int p = blockIdx.x*128 + threadIdx.x;        // 65536 pixels total
  int b = p >> 14, rem = p & 16383;
  int h = rem >> 7, w = rem & 127;
  const float* xb = x + b*NCH*65536 + (h*2)*256 + (w*2);
  float r[NCH];
#pragma unroll
  for (int c = 0; c < NCH; c++){
    const float* xc = xb + c*65536;
    r[c] = fmaxf(fmaxf(xc[0], xc[1]), fmaxf(xc[256], xc[257]));
  }
  float* outp = g_y1 + b*C3*HW + rem;
  const float4* ws4 = (const float4*)ws;
  for (int o = 0; o < C3; o += 4){
    float a0=0.f,a1=0.f,a2=0.f,a3=0.f;
#pragma unroll
    for (int c = 0; c < NCH; c += 4){
      float4 w0 = ws4[((o+0)*NCH+c)>>2];
      float4 w1 = ws4[((o+1)*NCH+c)>>2];
      float4 w2 = ws4[((o+2)*NCH+c)>>2];
      float4 w3 = ws4[((o+3)*NCH+c)>>2];
      a0 = fmaf(w0.x,r[c],fmaf(w0.y,r[c+1],fmaf(w0.z,r[c+2],fmaf(w0.w,r[c+3],a0))));
      a1 = fmaf(w1.x,r[c],fmaf(w1.y,r[c+1],fmaf(w1.z,r[c+2],fmaf(w1.w,r[c+3],a1))));
      a2 = fmaf(w2.x,r[c],fmaf(w2.y,r[c+1],fmaf(w2.z,r[c+2],fmaf(w2.w,r[c+3],a2))));
      a3 = fmaf(w3.x,r[c],fmaf(w3.y,r[c+1],fmaf(w3.z,r[c+2],fmaf(w3.w,r[c+3],a3))));
    }
    outp[(o+0)*HW]=a0; outp[(o+1)*HW]=a1; outp[(o+2)*HW]=a2; outp[(o+3)*HW]=a3;
  }
}

// ---------------- depthwise 3x3, zero pad ----------------
__global__ void k_dw3(const float* __restrict__ wd){
  int ix = blockIdx.x*256 + threadIdx.x;
  if (ix >= BATCH*C3*HW) return;
  int w = ix & 127, h = (ix>>7)&127, bc = ix>>14;
  int ch = bc % C3;
  const float* src = g_y1 + bc*HW;
  float acc = 0.f;
#pragma unroll
  for (int dy = 0; dy < 3; dy++){
    int ih = h + dy - 1;
    if ((unsigned)ih >= 128u) continue;
#pragma unroll
    for (int dx = 0; dx < 3; dx++){
      int iw = w + dx - 1;
      if ((unsigned)iw >= 128u) continue;
      acc = fmaf(src[ih*128+iw], wd[ch*9 + dy*3 + dx], acc);
    }
  }
  g_qkv[ix] = acc;
}

// ---------------- channel sums of q ----------------
__global__ void k_sum(){
  __shared__ float red[256];
  int bc = blockIdx.x;                 // b*64+c
  int b = bc >> 6, c = bc & 63;
  const float* src = g_qkv + (b*C3 + c)*HW;
  float s = 0.f;
  for (int i = threadIdx.x; i < HW; i += 256) s += src[i];
  red[threadIdx.x] = s; __syncthreads();
  for (int st = 128; st > 0; st >>= 1){
    if (threadIdx.x < st) red[threadIdx.x] += red[threadIdx.x+st];
    __syncthreads();
  }
  if (threadIdx.x == 0) g_S[bc] = red[0];
}

// ---------------- Gram partials (deterministic split-K) ----------------
__global__ void k_gram(){
  __shared__ float sh[64][65];
  int b = blockIdx.y, sp = blockIdx.x;
  int tc = (threadIdx.x >> 4) << 2;
  int td = (threadIdx.x & 15) << 2;
  float acc[4][4];
#pragma unroll
  for (int i = 0; i < 4; i++)
#pragma unroll
    for (int j = 0; j < 4; j++) acc[i][j] = 0.f;
  const float* qb = g_qkv + b*C3*HW + sp*512;
  for (int ch = 0; ch < 8; ch++){
    int n0 = ch*64;
    for (int i = threadIdx.x; i < 4096; i += 256)
      sh[i>>6][i&63] = qb[(i>>6)*HW + n0 + (i&63)];
    __syncthreads();
    for (int n = 0; n < 64; n++){
      float a0=sh[tc][n],a1=sh[tc+1][n],a2=sh[tc+2][n],a3=sh[tc+3][n];
      float b0=sh[td][n],b1=sh[td+1][n],b2=sh[td+2][n],b3=sh[td+3][n];
      acc[0][0]+=a0*b0; acc[0][1]+=a0*b1; acc[0][2]+=a0*b2; acc[0][3]+=a0*b3;
      acc[1][0]+=a1*b0; acc[1][1]+=a1*b1; acc[1][2]+=a1*b2; acc[1][3]+=a1*b3;
      acc[2][0]+=a2*b0; acc[2][1]+=a2*b1; acc[2][2]+=a2*b2; acc[2][3]+=a2*b3;
      acc[3][0]+=a3*b0; acc[3][1]+=a3*b1; acc[3][2]+=a3*b2; acc[3][3]+=a3*b3;
    }
    __syncthreads();
  }
#pragma unroll
  for (int i = 0; i < 4; i++)
#pragma unroll
    for (int j = 0; j < 4; j++)
      g_Gpart[((b*32+sp)*64 + tc+i)*64 + td+j] = acc[i][j];
}

// ---------------- cov -> sim -> stable ranking ----------------
__global__ void k_stats(){
  __shared__ float covs[64][64];
  __shared__ float stds[64];
  __shared__ float sims[64];
  int b = blockIdx.x;
  for (int pr = threadIdx.x; pr < 4096; pr += 256){
    int c = pr>>6, d = pr&63;
    float g = 0.f;
    for (int s = 0; s < 32; s++) g += g_Gpart[((b*32+s)*64 + c)*64 + d];
    covs[c][d] = g - g_S[b*64+c]*g_S[b*64+d]*(1.0f/16384.0f);
  }
  __syncthreads();
  if (threadIdx.x < 64)
    stds[threadIdx.x] = sqrtf(covs[threadIdx.x][threadIdx.x] + 1e-8f);
  __syncthreads();
  if (threadIdx.x < 64){
    int c = threadIdx.x;
    float sc = stds[c], a = 0.f;
    for (int d = 0; d < 64; d++) a += covs[c][d] / fmaxf(sc*stds[d], 1e-8f);
    sims[c] = a * (1.0f/64.0f);
  }
  __syncthreads();
  if (threadIdx.x < 64){
    int c = threadIdx.x;
    float v = sims[c]; int r = 0;
    for (int d = 0; d < 64; d++){
      float u = sims[d];
      r += (u > v) || (u == v && d < c);    // stable argsort(-sim)
    }
    g_idx[b*64 + r] = c;
  }
}

// ---------------- block-local halo attention + gate + scatter ----------------
__global__ __launch_bounds__(64) void k_attn(const float* __restrict__ gatew,
    const float* __restrict__ gateb, const float* __restrict__ temp,
    const float* __restrict__ relh, const float* __restrict__ relw){
  __shared__ int   sc[HD];
  __shared__ float kn[NKEY][HD];
  __shared__ float vv[NKEY][HD];
  __shared__ float gws[HD*HD];
  __shared__ float gbs[HD];
  int tid = threadIdx.x;
  int g = blockIdx.y, b = blockIdx.z;
  if (tid < HD){
    sc[tid]  = g_idx[b*64 + g*HD + tid];
    gbs[tid] = gateb[g*HD + tid];
  }
  for (int i = tid; i < HD*HD; i += 64) gws[i] = gatew[g*HD*HD + i];
  __syncthreads();
  int bh = blockIdx.x >> 4, bw = blockIdx.x & 15;
  int h0 = bh*8, w0 = bw*8;
  // keys & values for the 10x10 halo neighborhood (zero-padded; rel emb added to pads too)
  for (int p = tid; p < NKEY; p += 64){
    int ry = p/10, rx = p - ry*10;
    int gh = h0 - 1 + ry, gw2 = w0 - 1 + rx;
    bool inb = ((unsigned)gh < 128u) && ((unsigned)gw2 < 128u);
    int posk = gh*128 + gw2;
    float ss = 0.f; float tmp[HD];
#pragma unroll
    for (int c = 0; c < HD; c++){
      float base = 0.f, vval = 0.f;
      if (inb){
        int off = (b*C3 + sc[c])*HW + posk;
        base = g_qkv[off + 64*HW];
        vval = g_qkv[off + 128*HW];
      }
      float rel = (c < 8) ? relh[(g*10+ry)*8 + c] : relw[(g*10+rx)*8 + (c-8)];
      float kv = base + rel;
      tmp[c] = kv; ss += kv*kv;
      vv[p][c] = vval;
    }
    float inv = 1.0f / fmaxf(sqrtf(ss), 1e-12f);
#pragma unroll
    for (int c = 0; c < HD; c++) kn[p][c] = tmp[c]*inv;
  }
  int qy = tid >> 3, qx = tid & 7;
  int pos = (h0+qy)*128 + (w0+qx);
  float qr[HD]; float ss = 0.f;
#pragma unroll
  for (int c = 0; c < HD; c++){
    float v = g_qkv[(b*C3 + sc[c])*HW + pos];
    qr[c] = v; ss += v*v;
  }
  float qs = __expf(temp[g]) / fmaxf(sqrtf(ss), 1e-12f);
  __syncthreads();
  // online softmax over 100 keys
  float m = -1e30f, s = 0.f, acc[HD];
#pragma unroll
  for (int c = 0; c < HD; c++) acc[c] = 0.f;
  for (int kp = 0; kp < NKEY; kp++){
    float d = 0.f;
#pragma unroll
    for (int c = 0; c < HD; c++) d = fmaf(qr[c], kn[kp][c], d);
    float l = d * qs;
    if (l > m){
      float f = __expf(m - l);
      s *= f;
#pragma unroll
      for (int c = 0; c < HD; c++) acc[c] *= f;
      m = l;
    }
    float pv = __expf(l - m);
    s += pv;
#pragma unroll
    for (int c = 0; c < HD; c++) acc[c] = fmaf(pv, vv[kp][c], acc[c]);
  }
  float invs = 1.0f / s;
#pragma unroll
  for (int o = 0; o < HD; o++){
    float ga = gbs[o];
#pragma unroll
    for (int c = 0; c < HD; c++) ga = fmaf(gws[o*HD+c], qr[c], ga);
    float sig = 1.0f/(1.0f + __expf(-ga));
    g_attn[(b*NCH + sc[o])*HW + pos] = acc[o]*invs*sig;   // scatter to original channel
  }
}

// ---------------- MLP stage 1: gating conv + exact gelu * mixed ----------------
__global__ __launch_bounds__(128) void k_mlp_gate(const float* __restrict__ wg,
                                                  const float* __restrict__ bg){
  __shared__ float ws[4096];
  __shared__ float bs[64];
  for (int i = threadIdx.x; i < 4096; i += 128) ws[i] = wg[i];
  if (threadIdx.x < 64) bs[threadIdx.x] = bg[threadIdx.x];
  __syncthreads();
  int p = blockIdx.x*128 + threadIdx.x;
  int b = p >> 14, pos = p & 16383;
  const float* ao = g_attn + b*NCH*HW + pos;
  const float* qk = g_qkv  + b*C3*HW + pos;
  float mx[64];
#pragma unroll
  for (int c = 0; c < 64; c++) mx[c] = ao[c*HW] + qk[c*HW] + qk[(64+c)*HW];
  float* gout = g_y1 + b*NCH*HW + pos;   // reuse scratch
  const float4* ws4 = (const float4*)ws;
  for (int o = 0; o < 64; o += 4){
    float a0=bs[o],a1=bs[o+1],a2=bs[o+2],a3=bs[o+3];
#pragma unroll
    for (int c = 0; c < 64; c += 4){
      float4 w0 = ws4[((o+0)*64+c)>>2];
      float4 w1 = ws4[((o+1)*64+c)>>2];
      float4 w2 = ws4[((o+2)*64+c)>>2];
      float4 w3 = ws4[((o+3)*64+c)>>2];
      a0 = fmaf(w0.x,mx[c],fmaf(w0.y,mx[c+1],fmaf(w0.z,mx[c+2],fmaf(w0.w,mx[c+3],a0))));
      a1 = fmaf(w1.x,mx[c],fmaf(w1.y,mx[c+1],fmaf(w1.z,mx[c+2],fmaf(w1.w,mx[c+3],a1))));
      a2 = fmaf(w2.x,mx[c],fmaf(w2.y,mx[c+1],fmaf(w2.z,mx[c+2],fmaf(w2.w,mx[c+3],a2))));
      a3 = fmaf(w3.x,mx[c],fmaf(w3.y,mx[c+1],fmaf(w3.z,mx[c+2],fmaf(w3.w,mx[c+3],a3))));
    }
    float m0 = ao[(o+0)*HW] + qk[(o+0)*HW] + qk[(64+o+0)*HW];
    float m1 = ao[(o+1)*HW] + qk[(o+1)*HW] + qk[(64+o+1)*HW];
    float m2 = ao[(o+2)*HW] + qk[(o+2)*HW] + qk[(64+o+2)*HW];
    float m3 = ao[(o+3)*HW] + qk[(o+3)*HW] + qk[(64+o+3)*HW];
    gout[(o+0)*HW] = 0.5f*a0*(1.0f+erff(a0*0.70710678118f))*m0;
    gout[(o+1)*HW] = 0.5f*a1*(1.0f+erff(a1*0.70710678118f))*m1;
    gout[(o+2)*HW] = 0.5f*a2*(1.0f+erff(a2*0.70710678118f))*m2;
    gout[(o+3)*HW] = 0.5f*a3*(1.0f+erff(a3*0.70710678118f))*m3;
  }
}

// ---------------- MLP stage 2: down(32) + up(64) + residual add ----------------
__global__ __launch_bounds__(128) void k_mlp_du(const float* __restrict__ wd,
    const float* __restrict__ bd, const float* __restrict__ wu,
    const float* __restrict__ bu){
  __shared__ float wds[2048];
  __shared__ float wus[2048];
  __shared__ float bds[32];
  __shared__ float bus[64];
  for (int i = threadIdx.x; i < 2048; i += 128){ wds[i]=wd[i]; wus[i]=wu[i]; }
  if (threadIdx.x < 32) bds[threadIdx.x] = bd[threadIdx.x];
  if (threadIdx.x < 64) bus[threadIdx.x] = bu[threadIdx.x];
  __syncthreads();
  int p = blockIdx.x*128 + threadIdx.x;
  int b = p >> 14, pos = p & 16383;
  const float* gin = g_y1 + b*NCH*HW + pos;
  float gv[64];
#pragma unroll
  for (int c = 0; c < 64; c++) gv[c] = gin[c*HW];
  float dv[32];
  const float4* wd4 = (const float4*)wds;
#pragma unroll
  for (int j = 0; j < 32; j++){
    float a = bds[j];
#pragma unroll
    for (int c = 0; c < 64; c += 4){
      float4 w = wd4[(j*64+c)>>2];
      a = fmaf(w.x,gv[c],fmaf(w.y,gv[c+1],fmaf(w.z,gv[c+2],fmaf(w.w,gv[c+3],a))));
    }
    dv[j] = a;
  }
  const float* ao = g_attn + b*NCH*HW + pos;
  float* o2 = g_y1 + BATCH*NCH*HW + b*NCH*HW + pos;
  const float4* wu4 = (const float4*)wus;
  for (int o = 0; o < 64; o += 4){
    float a0=bus[o],a1=bus[o+1],a2=bus[o+2],a3=bus[o+3];
#pragma unroll
    for (int j = 0; j < 32; j += 4){
      float4 w0 = wu4[((o+0)*32+j)>>2];
      float4 w1 = wu4[((o+1)*32+j)>>2];
      float4 w2 = wu4[((o+2)*32+j)>>2];
      float4 w3 = wu4[((o+3)*32+j)>>2];
      a0 = fmaf(w0.x,dv[j],fmaf(w0.y,dv[j+1],fmaf(w0.z,dv[j+2],fmaf(w0.w,dv[j+3],a0))));
      a1 = fmaf(w1.x,dv[j],fmaf(w1.y,dv[j+1],fmaf(w1.z,dv[j+2],fmaf(w1.w,dv[j+3],a1))));
      a2 = fmaf(w2.x,dv[j],fmaf(w2.y,dv[j+1],fmaf(w2.z,dv[j+2],fmaf(w2.w,dv[j+3],a2))));
      a3 = fmaf(w3.x,dv[j],fmaf(w3.y,dv[j+1],fmaf(w3.z,dv[j+2],fmaf(w3.w,dv[j+3],a3))));
    }
    o2[(o+0)*HW] = ao[(o+0)*HW] + a0;
    o2[(o+1)*HW] = ao[(o+1)*HW] + a1;
    o2[(o+2)*HW] = ao[(o+2)*HW] + a2;
    o2[(o+3)*HW] = ao[(o+3)*HW] + a3;
  }
}

// ---------------- MLP stage 3: proj (64x64, no bias) ----------------
__global__ __launch_bounds__(128) void k_mlp_proj(const float* __restrict__ wp){
  __shared__ float ws[4096];
  for (int i = threadIdx.x; i < 4096; i += 128) ws[i] = wp[i];
  __syncthreads();
  int p = blockIdx.x*128 + threadIdx.x;
  int b = p >> 14, pos = p & 16383;
  const float* o2 = g_y1 + BATCH*NCH*HW + b*NCH*HW + pos;
  float v[64];
#pragma unroll
  for (int c = 0; c < 64; c++) v[c] = o2[c*HW];
  float* outp = g_out3 + b*NCH*HW + pos;
  const float4* ws4 = (const float4*)ws;
  for (int o = 0; o < 64; o += 4){
    float a0=0.f,a1=0.f,a2=0.f,a3=0.f;
#pragma unroll
    for (int c = 0; c < 64; c += 4){
      float4 w0 = ws4[((o+0)*64+c)>>2];
      float4 w1 = ws4[((o+1)*64+c)>>2];
      float4 w2 = ws4[((o+2)*64+c)>>2];
      float4 w3 = ws4[((o+3)*64+c)>>2];
      a0 = fmaf(w0.x,v[c],fmaf(w0.y,v[c+1],fmaf(w0.z,v[c+2],fmaf(w0.w,v[c+3],a0))));
      a1 = fmaf(w1.x,v[c],fmaf(w1.y,v[c+1],fmaf(w1.z,v[c+2],fmaf(w1.w,v[c+3],a1))));
      a2 = fmaf(w2.x,v[c],fmaf(w2.y,v[c+1],fmaf(w2.z,v[c+2],fmaf(w2.w,v[c+3],a2))));
      a3 = fmaf(w3.x,v[c],fmaf(w3.y,v[c+1],fmaf(w3.z,v[c+2],fmaf(w3.w,v[c+3],a3))));
    }
    outp[(o+0)*HW]=a0; outp[(o+1)*HW]=a1; outp[(o+2)*HW]=a2; outp[(o+3)*HW]=a3;
  }
}

// ---------------- depthwise 3x3, reflect pad, + bias ----------------
__global__ void k_lp(const float* __restrict__ wl, const float* __restrict__ bl){
  int ix = blockIdx.x*256 + threadIdx.x;
  if (ix >= BATCH*NCH*HW) return;
  int w = ix & 127, h = (ix>>7)&127, bc = ix>>14;
  int ch = bc & 63;
  const float* src = g_out3 + bc*HW;
  float acc = bl[ch];
#pragma unroll
  for (int dy = 0; dy < 3; dy++){
    int ih = h + dy - 1;
    ih = (ih < 0) ? -ih : ((ih > 127) ? 254-ih : ih);
#pragma unroll
    for (int dx = 0; dx < 3; dx++){
      int iw = w + dx - 1;
      iw = (iw < 0) ? -iw : ((iw > 127) ? 254-iw : iw);
      acc = fmaf(src[ih*128+iw], wl[ch*9 + dy*3 + dx], acc);
    }
  }
  g_lp[ix] = acc;
}

// ---------------- bilinear x2 upsample, align_corners ----------------
__global__ void k_up(float* __restrict__ outp){
  int ix = blockIdx.x*256 + threadIdx.x;     // 16777216 exactly
  int X = ix & 255, Y = (ix>>8)&255, bc = ix>>16;
  float cy = Y * (127.0f/255.0f);
  int y0 = (int)cy; if (y0 > 126) y0 = 126;
  float wy = cy - (float)y0;
  float cx = X * (127.0f/255.0f);
  int x0 = (int)cx; if (x0 > 126) x0 = 126;
  float wx = cx - (float)x0;
  const float* t = g_lp + bc*HW;
  float v00 = t[y0*128 + x0],     v01 = t[y0*128 + x0 + 1];
  float v10 = t[y0*128 + 128 + x0], v11 = t[y0*128 + 128 + x0 + 1];
  float u0 = v00*(1.0f-wy) + v10*wy;
  float u1 = v01*(1.0f-wy) + v11*wy;
  outp[ix] = u0*(1.0f-wx) + u1*wx;
}

// ---------------- launch ----------------
extern "C" void kernel_launch(void* const* d_in, const int* in_sizes, int n_in,
                              void* d_out, int out_size){
  const float* x     = (const float*)d_in[0];
  const float* qkvw  = (const float*)d_in[1];
  const float* lcew  = (const float*)d_in[2];
  const float* gatew = (const float*)d_in[3];
  const float* gateb = (const float*)d_in[4];
  const float* temp  = (const float*)d_in[5];
  const float* relh  = (const float*)d_in[6];
  const float* relw  = (const float*)d_in[7];
  const float* downw = (const float*)d_in[8];
  const float* downb = (const float*)d_in[9];
  const float* upw   = (const float*)d_in[10];
  const float* upb   = (const float*)d_in[11];
  const float* gatingw = (const float*)d_in[12];
  const float* gatingb = (const float*)d_in[13];
  const float* projw = (const float*)d_in[14];
  const float* lpw   = (const float*)d_in[15];
  const float* lpb   = (const float*)d_in[16];
  float* outp = (float*)d_out;

  k_pool_qkv<<<512, 128>>>(x, qkvw);
  k_dw3<<<(BATCH*C3*HW)/256, 256>>>(lcew);
  k_sum<<<BATCH*NCH, 256>>>();
  k_gram<<<dim3(32, BATCH), 256>>>();
  k_stats<<<BATCH, 256>>>();
  k_attn<<<dim3(256, NHEADS, BATCH), 64>>>(gatew, gateb, temp, relh, relw);
  k_mlp_gate<<<512, 128>>>(gatingw, gatingb);
  k_mlp_du<<<512, 128>>>(downw, downb, upw, upb);
  k_mlp_proj<<<512, 128>>>(projw);
  k_lp<<<(BATCH*NCH*HW)/256, 256>>>(lpw, lpb);
  k_up<<<65536, 256>>>(outp);
}

// round 2
// speedup vs baseline: 1.0208x; 1.0208x over previous
#include <cuda_runtime.h>
#include <math.h>

#define BATCH 4
#define HH 128
#define WW 128
#define HW 16384
#define NCH 64
#define C3 192
#define NHEADS 4
#define HD 16
#define NKEY 100

typedef unsigned long long u64;

// ---------------- f32x2 packed-math helpers (sm_100+) ----------------
__device__ __forceinline__ u64 pack2(float a, float b){
  u64 r; asm("mov.b64 %0, {%1, %2};" : "=l"(r) : "f"(a), "f"(b)); return r;
}
__device__ __forceinline__ void fma2(u64 &d, u64 a, u64 b){
  asm("fma.rn.f32x2 %0, %1, %2, %0;" : "+l"(d) : "l"(a), "l"(b));
}
__device__ __forceinline__ void unpack2(u64 a, float &x, float &y){
  asm("mov.b64 {%0, %1}, %2;" : "=f"(x), "=f"(y) : "l"(a));
}
__device__ __forceinline__ float hadd2(u64 a){
  float x, y; unpack2(a, x, y); return x + y;
}
union F4U { float4 f; ulonglong2 u; };

// ---------------- scratch (static device memory; no allocs) ----------------
__device__ __align__(16) float g_y1[BATCH*C3*HW];    // conv1x1 out
__device__ __align__(16) float g_qkv[BATCH*C3*HW];   // after depthwise 3x3: q|k|v
__device__ __align__(16) float g_attn[BATCH*NCH*HW]; // attention output (original channels)
__device__ __align__(16) float g_out3[BATCH*NCH*HW]; // after proj
__device__ __align__(16) float g_lp[BATCH*NCH*HW];   // after reflect dw3x3
__device__ float g_S[BATCH*NCH];
__device__ __align__(16) float g_Gpart[BATCH*128*NCH*NCH];
__device__ int   g_idx[BATCH*NCH];

// ---------------- fused maxpool2 + conv1x1 (64 -> 192), 2 px/thread ----------------
__global__ __launch_bounds__(128) void k_pool_qkv(const float* __restrict__ x,
                                                  const float* __restrict__ wq){
  __shared__ __align__(16) float ws[C3*NCH];                 // 48KB
  for (int i = threadIdx.x; i < C3*NCH; i += 128) ws[i] = wq[i];
  __syncthreads();
  int t = blockIdx.x*128 + threadIdx.x;        // 32768 threads, 2 pixels each
  int p0 = t*2;
  int b = p0 >> 14, rem = p0 & 16383;
  int h = rem >> 7, w = rem & 127;             // w even
  const float* xb = x + b*NCH*65536 + (h*2)*256 + (w*2);
  u64 xa[32], xbp[32];                          // channel-pair packs for px0, px1
#pragma unroll
  for (int c = 0; c < NCH; c += 2){
    const float* xc0 = xb + c*65536;
    float4 r0 = *(const float4*)xc0;
    float4 r1 = *(const float4*)(xc0 + 256);
    float p00 = fmaxf(fmaxf(r0.x, r0.y), fmaxf(r1.x, r1.y));
    float p01 = fmaxf(fmaxf(r0.z, r0.w), fmaxf(r1.z, r1.w));
    const float* xc1 = xc0 + 65536;
    float4 s0 = *(const float4*)xc1;
    float4 s1 = *(const float4*)(xc1 + 256);
    float p10 = fmaxf(fmaxf(s0.x, s0.y), fmaxf(s1.x, s1.y));
    float p11 = fmaxf(fmaxf(s0.z, s0.w), fmaxf(s1.z, s1.w));
    xa[c>>1]  = pack2(p00, p10);
    xbp[c>>1] = pack2(p01, p11);
  }
  float* outp = g_y1 + b*C3*HW + rem;
  const ulonglong2* wsu = (const ulonglong2*)ws;   // 16 ull2 per 64-float row
  for (int o = 0; o < C3; o += 4){
    u64 a0p0=0,a1p0=0,a2p0=0,a3p0=0, a0p1=0,a1p1=0,a2p1=0,a3p1=0;
#pragma unroll
    for (int cc4 = 0; cc4 < 16; cc4++){
      ulonglong2 w0 = wsu[(o+0)*16 + cc4];
      ulonglong2 w1 = wsu[(o+1)*16 + cc4];
      ulonglong2 w2 = wsu[(o+2)*16 + cc4];
      ulonglong2 w3 = wsu[(o+3)*16 + cc4];
      u64 x0 = xa[2*cc4], x1 = xa[2*cc4+1];
      u64 y0 = xbp[2*cc4], y1 = xbp[2*cc4+1];
      fma2(a0p0, w0.x, x0); fma2(a0p0, w0.y, x1);
      fma2(a1p0, w1.x, x0); fma2(a1p0, w1.y, x1);
      fma2(a2p0, w2.x, x0); fma2(a2p0, w2.y, x1);
      fma2(a3p0, w3.x, x0); fma2(a3p0, w3.y, x1);
      fma2(a0p1, w0.x, y0); fma2(a0p1, w0.y, y1);
      fma2(a1p1, w1.x, y0); fma2(a1p1, w1.y, y1);
      fma2(a2p1, w2.x, y0); fma2(a2p1, w2.y, y1);
      fma2(a3p1, w3.x, y0); fma2(a3p1, w3.y, y1);
    }
    *(float2*)(outp + (o+0)*HW) = make_float2(hadd2(a0p0), hadd2(a0p1));
    *(float2*)(outp + (o+1)*HW) = make_float2(hadd2(a1p0), hadd2(a1p1));
    *(float2*)(outp + (o+2)*HW) = make_float2(hadd2(a2p0), hadd2(a2p1));
    *(float2*)(outp + (o+3)*HW) = make_float2(hadd2(a3p0), hadd2(a3p1));
  }
}

// ---------------- depthwise 3x3, zero pad ----------------
__global__ void k_dw3(const float* __restrict__ wd){
  int ix = blockIdx.x*256 + threadIdx.x;
  if (ix >= BATCH*C3*HW) return;
  int w = ix & 127, h = (ix>>7)&127, bc = ix>>14;
  int ch = bc % C3;
  const float* src = g_y1 + bc*HW;
  float acc = 0.f;
#pragma unroll
  for (int dy = 0; dy < 3; dy++){
    int ih = h + dy - 1;
    if ((unsigned)ih >= 128u) continue;
#pragma unroll
    for (int dx = 0; dx < 3; dx++){
      int iw = w + dx - 1;
      if ((unsigned)iw >= 128u) continue;
      acc = fmaf(src[ih*128+iw], wd[ch*9 + dy*3 + dx], acc);
    }
  }
  g_qkv[ix] = acc;
}

// ---------------- channel sums of q ----------------
__global__ void k_sum(){
  __shared__ float red[256];
  int bc = blockIdx.x;                 // b*64+c
  int b = bc >> 6, c = bc & 63;
  const float* src = g_qkv + (b*C3 + c)*HW;
  float s = 0.f;
  for (int i = threadIdx.x; i < HW; i += 256) s += src[i];
  red[threadIdx.x] = s; __syncthreads();
  for (int st = 128; st > 0; st >>= 1){
    if (threadIdx.x < st) red[threadIdx.x] += red[threadIdx.x+st];
    __syncthreads();
  }
  if (threadIdx.x == 0) g_S[bc] = red[0];
}

// ---------------- Gram partials: 128 splits, xor-swizzled smem, f32x2 ----------------
__global__ __launch_bounds__(256) void k_gram(){
  __shared__ __align__(16) float sh[64*128];   // [c][n] with xor swizzle at float4 grain
  int b = blockIdx.y, sp = blockIdx.x;         // sp in [0,128)
  int tid = threadIdx.x;
  int tc = (tid >> 4) << 2;
  int td = (tid & 15) << 2;
  const float* qb = g_qkv + b*C3*HW + sp*128;
  float4* sh4 = (float4*)sh;
  for (int i = tid; i < 2048; i += 256){
    int c = i >> 5, nn4 = i & 31;
    sh4[c*32 + (nn4 ^ (c>>2))] = *(const float4*)(qb + c*HW + nn4*4);
  }
  __syncthreads();
  u64 acc[4][4];
#pragma unroll
  for (int i = 0; i < 4; i++)
#pragma unroll
    for (int j = 0; j < 4; j++) acc[i][j] = 0ULL;
  const F4U* shf = (const F4U*)sh;
  for (int nn4 = 0; nn4 < 32; nn4++){
    F4U av[4], bv[4];
#pragma unroll
    for (int i = 0; i < 4; i++){ int r = tc + i; av[i] = shf[r*32 + (nn4 ^ (r>>2))]; }
#pragma unroll
    for (int j = 0; j < 4; j++){ int r = td + j; bv[j] = shf[r*32 + (nn4 ^ (r>>2))]; }
#pragma unroll
    for (int i = 0; i < 4; i++)
#pragma unroll
      for (int j = 0; j < 4; j++){
        fma2(acc[i][j], av[i].u.x, bv[j].u.x);
        fma2(acc[i][j], av[i].u.y, bv[j].u.y);
      }
  }
#pragma unroll
  for (int i = 0; i < 4; i++)
#pragma unroll
    for (int j = 0; j < 4; j++)
      g_Gpart[((b*128+sp)*64 + tc+i)*64 + td+j] = hadd2(acc[i][j]);
}

// ---------------- cov -> sim -> stable ranking ----------------
__global__ void k_stats(){
  __shared__ float covs[64][64];
  __shared__ float stds[64];
  __shared__ float sims[64];
  int b = blockIdx.x;
  for (int pr = threadIdx.x; pr < 4096; pr += 256){
    int c = pr>>6, d = pr&63;
    float g = 0.f;
    for (int s = 0; s < 128; s++) g += g_Gpart[((b*128+s)*64 + c)*64 + d];
    covs[c][d] = g - g_S[b*64+c]*g_S[b*64+d]*(1.0f/16384.0f);
  }
  __syncthreads();
  if (threadIdx.x < 64)
    stds[threadIdx.x] = sqrtf(covs[threadIdx.x][threadIdx.x] + 1e-8f);
  __syncthreads();
  if (threadIdx.x < 64){
    int c = threadIdx.x;
    float sc = stds[c], a = 0.f;
    for (int d = 0; d < 64; d++) a += covs[c][d] / fmaxf(sc*stds[d], 1e-8f);
    sims[c] = a * (1.0f/64.0f);
  }
  __syncthreads();
  if (threadIdx.x < 64){
    int c = threadIdx.x;
    float v = sims[c]; int r = 0;
    for (int d = 0; d < 64; d++){
      float u = sims[d];
      r += (u > v) || (u == v && d < c);    // stable argsort(-sim)
    }
    g_idx[b*64 + r] = c;
  }
}

// ---------------- block-local halo attention + gate + scatter ----------------
// logits are cosine * exp(temp) -> bounded by E = exp(temp): no online max needed.
__global__ __launch_bounds__(64) void k_attn(const float* __restrict__ gatew,
    const float* __restrict__ gateb, const float* __restrict__ temp,
    const float* __restrict__ relh, const float* __restrict__ relw){
  __shared__ int   sc[HD];
  __shared__ __align__(16) float kn[NKEY][HD];
  __shared__ __align__(16) float vv[NKEY][HD];
  __shared__ __align__(16) float gws[HD*HD];
  __shared__ float gbs[HD];
  int tid = threadIdx.x;
  int g = blockIdx.y, b = blockIdx.z;
  if (tid < HD){
    sc[tid]  = g_idx[b*64 + g*HD + tid];
    gbs[tid] = gateb[g*HD + tid];
  }
  for (int i = tid; i < HD*HD; i += 64) gws[i] = gatew[g*HD*HD + i];
  __syncthreads();
  int bh = blockIdx.x >> 4, bw = blockIdx.x & 15;
  int h0 = bh*8, w0 = bw*8;
  for (int p = tid; p < NKEY; p += 64){
    int ry = p/10, rx = p - ry*10;
    int gh = h0 - 1 + ry, gw2 = w0 - 1 + rx;
    bool inb = ((unsigned)gh < 128u) && ((unsigned)gw2 < 128u);
    int posk = gh*128 + gw2;
    float ss = 0.f; float tmp[HD];
#pragma unroll
    for (int c = 0; c < HD; c++){
      float base = 0.f, vval = 0.f;
      if (inb){
        int off = (b*C3 + sc[c])*HW + posk;
        base = g_qkv[off + 64*HW];
        vval = g_qkv[off + 128*HW];
      }
      float rel = (c < 8) ? relh[(g*10+ry)*8 + c] : relw[(g*10+rx)*8 + (c-8)];
      float kv = base + rel;
      tmp[c] = kv; ss += kv*kv;
      vv[p][c] = vval;
    }
    float inv = 1.0f / fmaxf(sqrtf(ss), 1e-12f);
#pragma unroll
    for (int c = 0; c < HD; c++) kn[p][c] = tmp[c]*inv;
  }
  int qy = tid >> 3, qx = tid & 7;
  int pos = (h0+qy)*128 + (w0+qx);
  float qraw[HD]; float ss = 0.f;
#pragma unroll
  for (int c = 0; c < HD; c++){
    float v = g_qkv[(b*C3 + sc[c])*HW + pos];
    qraw[c] = v; ss += v*v;
  }
  u64 qr2[8];
#pragma unroll
  for (int c = 0; c < HD; c += 2) qr2[c>>1] = pack2(qraw[c], qraw[c+1]);
  float E  = __expf(temp[g]);
  float qs = E / fmaxf(sqrtf(ss), 1e-12f);
  __syncthreads();
  float s = 0.f;
  u64 acc2[8];
#pragma unroll
  for (int i = 0; i < 8; i++) acc2[i] = 0ULL;
#pragma unroll 2
  for (int kp = 0; kp < NKEY; kp++){
    const ulonglong2* kk = (const ulonglong2*)kn[kp];
    ulonglong2 k0 = kk[0], k1 = kk[1], k2 = kk[2], k3 = kk[3];
    u64 da = 0ULL, db = 0ULL;
    fma2(da, qr2[0], k0.x); fma2(db, qr2[1], k0.y);
    fma2(da, qr2[2], k1.x); fma2(db, qr2[3], k1.y);
    fma2(da, qr2[4], k2.x); fma2(db, qr2[5], k2.y);
    fma2(da, qr2[6], k3.x); fma2(db, qr2[7], k3.y);
    float l = (hadd2(da) + hadd2(db)) * qs;
    float pv = __expf(l - E);
    s += pv;
    u64 pv2 = pack2(pv, pv);
    const ulonglong2* vk = (const ulonglong2*)vv[kp];
    ulonglong2 v0 = vk[0], v1 = vk[1], v2 = vk[2], v3 = vk[3];
    fma2(acc2[0], pv2, v0.x); fma2(acc2[1], pv2, v0.y);
    fma2(acc2[2], pv2, v1.x); fma2(acc2[3], pv2, v1.y);
    fma2(acc2[4], pv2, v2.x); fma2(acc2[5], pv2, v2.y);
    fma2(acc2[6], pv2, v3.x); fma2(acc2[7], pv2, v3.y);
  }
  float invs = 1.0f / s;
  float accv[HD];
#pragma unroll
  for (int i = 0; i < 8; i++) unpack2(acc2[i], accv[2*i], accv[2*i+1]);
  const ulonglong2* gw2 = (const ulonglong2*)gws;
#pragma unroll
  for (int o = 0; o < HD; o++){
    u64 a = 0ULL;
#pragma unroll
    for (int cc4 = 0; cc4 < 4; cc4++){
      ulonglong2 w = gw2[o*4 + cc4];
      fma2(a, w.x, qr2[2*cc4]); fma2(a, w.y, qr2[2*cc4+1]);
    }
    float ga = gbs[o] + hadd2(a);
    float sig = 1.0f/(1.0f + __expf(-ga));
    g_attn[(b*NCH + sc[o])*HW + pos] = accv[o]*invs*sig;
  }
}

// ---------------- fully fused MLP: gate -> gelu*mixed -> down -> up(+res) -> proj ----------------
__global__ __launch_bounds__(128) void k_mlp(const float* __restrict__ wg_g,
    const float* __restrict__ bg_g, const float* __restrict__ wd_g,
    const float* __restrict__ bd_g, const float* __restrict__ wu_g,
    const float* __restrict__ bu_g, const float* __restrict__ wp_g){
  __shared__ __align__(16) float wg[4096];
  __shared__ __align__(16) float wdn[2048];
  __shared__ __align__(16) float wup[2048];
  __shared__ __align__(16) float wpj[4096];
  __shared__ float bg[64], bdn[32], bup[64];
  for (int i = threadIdx.x; i < 4096; i += 128){ wg[i] = wg_g[i]; wpj[i] = wp_g[i]; }
  for (int i = threadIdx.x; i < 2048; i += 128){ wdn[i] = wd_g[i]; wup[i] = wu_g[i]; }
  if (threadIdx.x < 64) bg[threadIdx.x]  = bg_g[threadIdx.x];
  if (threadIdx.x < 32) bdn[threadIdx.x] = bd_g[threadIdx.x];
  if (threadIdx.x < 64) bup[threadIdx.x] = bu_g[threadIdx.x];
  __syncthreads();
  int p = blockIdx.x*128 + threadIdx.x;
  int b = p >> 14, pos = p & 16383;
  const float* ao = g_attn + b*NCH*HW + pos;
  const float* qk = g_qkv  + b*C3*HW + pos;
  u64 ao2[32], mx2[32];
#pragma unroll
  for (int c = 0; c < 64; c += 2){
    float a0 = ao[c*HW],     a1 = ao[(c+1)*HW];
    float m0 = a0 + qk[c*HW]     + qk[(64+c)*HW];
    float m1 = a1 + qk[(c+1)*HW] + qk[(64+c+1)*HW];
    ao2[c>>1] = pack2(a0, a1);
    mx2[c>>1] = pack2(m0, m1);
  }
  // gate conv + exact gelu * mixed
  u64 gg2[32];
  const ulonglong2* wg2 = (const ulonglong2*)wg;
#pragma unroll 4
  for (int o = 0; o < 64; o += 2){
    u64 a0 = 0ULL, a1 = 0ULL;
#pragma unroll
    for (int cc4 = 0; cc4 < 16; cc4++){
      ulonglong2 w0 = wg2[(o+0)*16 + cc4];
      ulonglong2 w1 = wg2[(o+1)*16 + cc4];
      fma2(a0, w0.x, mx2[2*cc4]); fma2(a0, w0.y, mx2[2*cc4+1]);
      fma2(a1, w1.x, mx2[2*cc4]); fma2(a1, w1.y, mx2[2*cc4+1]);
    }
    float g0 = bg[o]   + hadd2(a0);
    float g1 = bg[o+1] + hadd2(a1);
    float m0, m1; unpack2(mx2[o>>1], m0, m1);
    g0 = 0.5f*g0*(1.0f + erff(g0*0.70710678118f)) * m0;
    g1 = 0.5f*g1*(1.0f + erff(g1*0.70710678118f)) * m1;
    gg2[o>>1] = pack2(g0, g1);
  }
  // down (64 -> 32)
  float dvs[32];
  const ulonglong2* wd2 = (const ulonglong2*)wdn;
#pragma unroll 4
  for (int j = 0; j < 32; j++){
    u64 a = 0ULL;
#pragma unroll
    for (int cc4 = 0; cc4 < 16; cc4++){
      ulonglong2 w = wd2[j*16 + cc4];
      fma2(a, w.x, gg2[2*cc4]); fma2(a, w.y, gg2[2*cc4+1]);
    }
    dvs[j] = bdn[j] + hadd2(a);
  }
  u64 dv2[16];
#pragma unroll
  for (int j = 0; j < 32; j += 2) dv2[j>>1] = pack2(dvs[j], dvs[j+1]);
  // up (32 -> 64) + residual (attention out)
  u64 o22[32];
  const ulonglong2* wu2 = (const ulonglong2*)wup;
#pragma unroll 4
  for (int o = 0; o < 64; o += 2){
    u64 a0 = 0ULL, a1 = 0ULL;
#pragma unroll
    for (int jj4 = 0; jj4 < 8; jj4++){
      ulonglong2 w0 = wu2[(o+0)*8 + jj4];
      ulonglong2 w1 = wu2[(o+1)*8 + jj4];
      fma2(a0, w0.x, dv2[2*jj4]); fma2(a0, w0.y, dv2[2*jj4+1]);
      fma2(a1, w1.x, dv2[2*jj4]); fma2(a1, w1.y, dv2[2*jj4+1]);
    }
    float r0, r1; unpack2(ao2[o>>1], r0, r1);
    o22[o>>1] = pack2(r0 + bup[o] + hadd2(a0), r1 + bup[o+1] + hadd2(a1));
  }
  // proj (64 -> 64, no bias)
  float* outp = g_out3 + b*NCH*HW + pos;
  const ulonglong2* wp2 = (const ulonglong2*)wpj;
#pragma unroll 4
  for (int o = 0; o < 64; o++){
    u64 a = 0ULL;
#pragma unroll
    for (int cc4 = 0; cc4 < 16; cc4++){
      ulonglong2 w = wp2[o*16 + cc4];
      fma2(a, w.x, o22[2*cc4]); fma2(a, w.y, o22[2*cc4+1]);
    }
    outp[o*HW] = hadd2(a);
  }
}

// ---------------- depthwise 3x3, reflect pad, + bias ----------------
__global__ void k_lp(const float* __restrict__ wl, const float* __restrict__ bl){
  int ix = blockIdx.x*256 + threadIdx.x;
  if (ix >= BATCH*NCH*HW) return;
  int w = ix & 127, h = (ix>>7)&127, bc = ix>>14;
  int ch = bc & 63;
  const float* src = g_out3 + bc*HW;
  float acc = bl[ch];
#pragma unroll
  for (int dy = 0; dy < 3; dy++){
    int ih = h + dy - 1;
    ih = (ih < 0) ? -ih : ((ih > 127) ? 254-ih : ih);
#pragma unroll
    for (int dx = 0; dx < 3; dx++){
      int iw = w + dx - 1;
      iw = (iw < 0) ? -iw : ((iw > 127) ? 254-iw : iw);
      acc = fmaf(src[ih*128+iw], wl[ch*9 + dy*3 + dx], acc);
    }
  }
  g_lp[ix] = acc;
}

// ---------------- bilinear x2 upsample, align_corners ----------------
__global__ void k_up(float* __restrict__ outp){
  int ix = blockIdx.x*256 + threadIdx.x;     // 16777216 exactly
  int X = ix & 255, Y = (ix>>8)&255, bc = ix>>16;
  float cy = Y * (127.0f/255.0f);
  int y0 = (int)cy; if (y0 > 126) y0 = 126;
  float wy = cy - (float)y0;
  float cx = X * (127.0f/255.0f);
  int x0 = (int)cx; if (x0 > 126) x0 = 126;
  float wx = cx - (float)x0;
  const float* t = g_lp + bc*HW;
  float v00 = t[y0*128 + x0],       v01 = t[y0*128 + x0 + 1];
  float v10 = t[y0*128 + 128 + x0], v11 = t[y0*128 + 128 + x0 + 1];
  float u0 = v00*(1.0f-wy) + v10*wy;
  float u1 = v01*(1.0f-wy) + v11*wy;
  outp[ix] = u0*(1.0f-wx) + u1*wx;
}

// ---------------- launch ----------------
extern "C" void kernel_launch(void* const* d_in, const int* in_sizes, int n_in,
                              void* d_out, int out_size){
  const float* x     = (const float*)d_in[0];
  const float* qkvw  = (const float*)d_in[1];
  const float* lcew  = (const float*)d_in[2];
  const float* gatew = (const float*)d_in[3];
  const float* gateb = (const float*)d_in[4];
  const float* temp  = (const float*)d_in[5];
  const float* relh  = (const float*)d_in[6];
  const float* relw  = (const float*)d_in[7];
  const float* downw = (const float*)d_in[8];
  const float* downb = (const float*)d_in[9];
  const float* upw   = (const float*)d_in[10];
  const float* upb   = (const float*)d_in[11];
  const float* gatingw = (const float*)d_in[12];
  const float* gatingb = (const float*)d_in[13];
  const float* projw = (const float*)d_in[14];
  const float* lpw   = (const float*)d_in[15];
  const float* lpb   = (const float*)d_in[16];
  float* outp = (float*)d_out;

  k_pool_qkv<<<256, 128>>>(x, qkvw);
  k_dw3<<<(BATCH*C3*HW)/256, 256>>>(lcew);
  k_sum<<<BATCH*NCH, 256>>>();
  k_gram<<<dim3(128, BATCH), 256>>>();
  k_stats<<<BATCH, 256>>>();
  k_attn<<<dim3(256, NHEADS, BATCH), 64>>>(gatew, gateb, temp, relh, relw);
  k_mlp<<<512, 128>>>(gatingw, gatingb, downw, downb, upw, upb, projw);
  k_lp<<<(BATCH*NCH*HW)/256, 256>>>(lpw, lpb);
  k_up<<<65536, 256>>>(outp);
}

// round 3
// speedup vs baseline: 1.1168x; 1.0940x over previous
#include <cuda_runtime.h>
#include <math.h>

#define BATCH 4
#define HW 16384
#define NCH 64
#define C3 192
#define NHEADS 4
#define HD 16
#define NKEY 100

typedef unsigned long long u64;

// ---------------- f32x2 packed-math helpers (sm_100+) ----------------
__device__ __forceinline__ u64 pack2(float a, float b){
  u64 r; asm("mov.b64 %0, {%1, %2};" : "=l"(r) : "f"(a), "f"(b)); return r;
}
__device__ __forceinline__ void fma2(u64 &d, u64 a, u64 b){
  asm("fma.rn.f32x2 %0, %1, %2, %0;" : "+l"(d) : "l"(a), "l"(b));
}
__device__ __forceinline__ void unpack2(u64 a, float &x, float &y){
  asm("mov.b64 {%0, %1}, %2;" : "=f"(x), "=f"(y) : "l"(a));
}
__device__ __forceinline__ float hadd2(u64 a){
  float x, y; unpack2(a, x, y); return x + y;
}
union F4U { float4 f; ulonglong2 u; };

// ---------------- scratch ----------------
__device__ __align__(16) float g_y1[BATCH*C3*HW];
__device__ __align__(16) float g_qkv[BATCH*C3*HW];
__device__ __align__(16) float g_attn[BATCH*NCH*HW];
__device__ __align__(16) float g_out3[BATCH*NCH*HW];
__device__ __align__(16) float g_lp[BATCH*NCH*HW];
__device__ __align__(16) float g_g[BATCH*NCH*HW];       // gelu-gated intermediate
__device__ float g_Sp[BATCH*128*NCH];
__device__ __align__(16) float g_Gpart[BATCH*128*NCH*NCH];
__device__ int   g_idx[BATCH*NCH];

// ---------------- fused maxpool2 + conv1x1 (64 -> 192), 1 px/thread ----------------
__global__ __launch_bounds__(128) void k_pool_qkv(const float* __restrict__ x,
                                                  const float* __restrict__ wq){
  __shared__ __align__(16) float ws[C3*NCH];                 // 48KB
  for (int i = threadIdx.x; i < C3*NCH; i += 128) ws[i] = wq[i];
  __syncthreads();
  int p = blockIdx.x*128 + threadIdx.x;        // 65536 pixels
  int b = p >> 14, rem = p & 16383;
  int h = rem >> 7, w = rem & 127;
  const float* xb = x + b*NCH*65536 + (h*2)*256 + (w*2);
  u64 a2[32];
#pragma unroll
  for (int c = 0; c < NCH; c += 2){
    const float* xc0 = xb + c*65536;
    float2 f0 = *(const float2*)xc0;
    float2 f1 = *(const float2*)(xc0 + 256);
    float p0 = fmaxf(fmaxf(f0.x, f0.y), fmaxf(f1.x, f1.y));
    const float* xc1 = xc0 + 65536;
    float2 g0 = *(const float2*)xc1;
    float2 g1 = *(const float2*)(xc1 + 256);
    float p1 = fmaxf(fmaxf(g0.x, g0.y), fmaxf(g1.x, g1.y));
    a2[c>>1] = pack2(p0, p1);
  }
  float* outp = g_y1 + b*C3*HW + rem;
  const ulonglong2* wsu = (const ulonglong2*)ws;   // 16 ull2 per 64-float row
  for (int o = 0; o < C3; o += 8){
    u64 acc[8];
#pragma unroll
    for (int i = 0; i < 8; i++) acc[i] = 0ULL;
#pragma unroll
    for (int cc4 = 0; cc4 < 16; cc4++){
      u64 x0 = a2[2*cc4], x1 = a2[2*cc4+1];
#pragma unroll
      for (int i = 0; i < 8; i++){
        ulonglong2 wv = wsu[(o+i)*16 + cc4];
        fma2(acc[i], wv.x, x0); fma2(acc[i], wv.y, x1);
      }
    }
#pragma unroll
    for (int i = 0; i < 8; i++) outp[(o+i)*HW] = hadd2(acc[i]);
  }
}

// ---------------- depthwise 3x3 zero pad, 4 px/thread ----------------
__global__ __launch_bounds__(256) void k_dw3(const float* __restrict__ wd){
  int t = blockIdx.x*256 + threadIdx.x;
  int base = t*4;
  int w4 = base & 127, h = (base>>7)&127, bc = base>>14;
  int ch = bc % C3;
  const float* src = g_y1 + bc*HW;
  const float* kk = wd + ch*9;
  float o0=0.f,o1=0.f,o2=0.f,o3=0.f;
#pragma unroll
  for (int dy = 0; dy < 3; dy++){
    int ih = h + dy - 1;
    if ((unsigned)ih >= 128u) continue;
    const float* r = src + ih*128 + w4;
    float4 m = *(const float4*)r;
    float lf = (w4 > 0)   ? r[-1] : 0.f;
    float rt = (w4 < 124) ? r[4]  : 0.f;
    float ka = kk[dy*3], kb = kk[dy*3+1], kc = kk[dy*3+2];
    o0 = fmaf(lf,ka,fmaf(m.x,kb,fmaf(m.y,kc,o0)));
    o1 = fmaf(m.x,ka,fmaf(m.y,kb,fmaf(m.z,kc,o1)));
    o2 = fmaf(m.y,ka,fmaf(m.z,kb,fmaf(m.w,kc,o2)));
    o3 = fmaf(m.z,ka,fmaf(m.w,kb,fmaf(rt,kc,o3)));
  }
  *(float4*)(g_qkv + base) = make_float4(o0,o1,o2,o3);
}

// ---------------- Gram partials + per-slice channel sums ----------------
__global__ __launch_bounds__(256) void k_gram(){
  __shared__ __align__(16) float sh[64*128];
  int b = blockIdx.y, sp = blockIdx.x;
  int tid = threadIdx.x;
  int tc = (tid >> 4) << 2;
  int td = (tid & 15) << 2;
  const float* qb = g_qkv + b*C3*HW + sp*128;
  float4* sh4 = (float4*)sh;
  for (int i = tid; i < 2048; i += 256){
    int c = i >> 5, nn4 = i & 31;
    sh4[c*32 + (nn4 ^ (c>>2))] = *(const float4*)(qb + c*HW + nn4*4);
  }
  __syncthreads();
  u64 acc[4][4];
#pragma unroll
  for (int i = 0; i < 4; i++)
#pragma unroll
    for (int j = 0; j < 4; j++) acc[i][j] = 0ULL;
  const F4U* shf = (const F4U*)sh;
  for (int nn4 = 0; nn4 < 32; nn4++){
    F4U av[4], bv[4];
#pragma unroll
    for (int i = 0; i < 4; i++){ int r = tc + i; av[i] = shf[r*32 + (nn4 ^ (r>>2))]; }
#pragma unroll
    for (int j = 0; j < 4; j++){ int r = td + j; bv[j] = shf[r*32 + (nn4 ^ (r>>2))]; }
#pragma unroll
    for (int i = 0; i < 4; i++)
#pragma unroll
      for (int j = 0; j < 4; j++){
        fma2(acc[i][j], av[i].u.x, bv[j].u.x);
        fma2(acc[i][j], av[i].u.y, bv[j].u.y);
      }
  }
#pragma unroll
  for (int i = 0; i < 4; i++)
#pragma unroll
    for (int j = 0; j < 4; j++)
      g_Gpart[((b*128+sp)*64 + tc+i)*64 + td+j] = hadd2(acc[i][j]);
  if (tid < 64){
    float s = 0.f;
    for (int nn4 = 0; nn4 < 32; nn4++){
      F4U f = shf[tid*32 + (nn4 ^ (tid>>2))];
      s += (f.f.x + f.f.y) + (f.f.z + f.f.w);
    }
    g_Sp[(b*128+sp)*64 + tid] = s;
  }
}

// ---------------- cov -> sim -> stable ranking ----------------
__global__ void k_stats(){
  __shared__ float covs[64][64];
  __shared__ float stds[64];
  __shared__ float sims[64];
  __shared__ float shS[64];
  int b = blockIdx.x;
  if (threadIdx.x < 64){
    float s = 0.f;
    for (int sp = 0; sp < 128; sp++) s += g_Sp[(b*128+sp)*64 + threadIdx.x];
    shS[threadIdx.x] = s;
  }
  __syncthreads();
  for (int pr = threadIdx.x; pr < 4096; pr += 256){
    int c = pr>>6, d = pr&63;
    float g = 0.f;
    for (int s = 0; s < 128; s++) g += g_Gpart[((b*128+s)*64 + c)*64 + d];
    covs[c][d] = g - shS[c]*shS[d]*(1.0f/16384.0f);
  }
  __syncthreads();
  if (threadIdx.x < 64)
    stds[threadIdx.x] = sqrtf(covs[threadIdx.x][threadIdx.x] + 1e-8f);
  __syncthreads();
  if (threadIdx.x < 64){
    int c = threadIdx.x;
    float sc = stds[c], a = 0.f;
    for (int d = 0; d < 64; d++) a += covs[c][d] / fmaxf(sc*stds[d], 1e-8f);
    sims[c] = a * (1.0f/64.0f);
  }
  __syncthreads();
  if (threadIdx.x < 64){
    int c = threadIdx.x;
    float v = sims[c]; int r = 0;
    for (int d = 0; d < 64; d++){
      float u = sims[d];
      r += (u > v) || (u == v && d < c);
    }
    g_idx[b*64 + r] = c;
  }
}

// ---------------- block-local halo attention + gate + scatter ----------------
__global__ __launch_bounds__(64) void k_attn(const float* __restrict__ gatew,
    const float* __restrict__ gateb, const float* __restrict__ temp,
    const float* __restrict__ relh, const float* __restrict__ relw){
  __shared__ int   sc[HD];
  __shared__ __align__(16) float kn[NKEY][HD];
  __shared__ __align__(16) float vv[NKEY][HD];
  __shared__ __align__(16) float gws[HD*HD];
  __shared__ float gbs[HD];
  int tid = threadIdx.x;
  int g = blockIdx.y, b = blockIdx.z;
  if (tid < HD){
    sc[tid]  = g_idx[b*64 + g*HD + tid];
    gbs[tid] = gateb[g*HD + tid];
  }
  for (int i = tid; i < HD*HD; i += 64) gws[i] = gatew[g*HD*HD + i];
  __syncthreads();
  int bh = blockIdx.x >> 4, bw = blockIdx.x & 15;
  int h0 = bh*8, w0 = bw*8;
  for (int p = tid; p < NKEY; p += 64){
    int ry = p/10, rx = p - ry*10;
    int gh = h0 - 1 + ry, gw2 = w0 - 1 + rx;
    bool inb = ((unsigned)gh < 128u) && ((unsigned)gw2 < 128u);
    int posk = gh*128 + gw2;
    float ss = 0.f; float tmp[HD];
#pragma unroll
    for (int c = 0; c < HD; c++){
      float base = 0.f, vval = 0.f;
      if (inb){
        int off = (b*C3 + sc[c])*HW + posk;
        base = g_qkv[off + 64*HW];
        vval = g_qkv[off + 128*HW];
      }
      float rel = (c < 8) ? relh[(g*10+ry)*8 + c] : relw[(g*10+rx)*8 + (c-8)];
      float kv = base + rel;
      tmp[c] = kv; ss += kv*kv;
      vv[p][c] = vval;
    }
    float inv = 1.0f / fmaxf(sqrtf(ss), 1e-12f);
#pragma unroll
    for (int c = 0; c < HD; c++) kn[p][c] = tmp[c]*inv;
  }
  int qy = tid >> 3, qx = tid & 7;
  int pos = (h0+qy)*128 + (w0+qx);
  float qraw[HD]; float ss = 0.f;
#pragma unroll
  for (int c = 0; c < HD; c++){
    float v = g_qkv[(b*C3 + sc[c])*HW + pos];
    qraw[c] = v; ss += v*v;
  }
  u64 qr2[8];
#pragma unroll
  for (int c = 0; c < HD; c += 2) qr2[c>>1] = pack2(qraw[c], qraw[c+1]);
  float E  = __expf(temp[g]);
  float qs = E / fmaxf(sqrtf(ss), 1e-12f);
  __syncthreads();
  float s = 0.f;
  u64 acc2[8];
#pragma unroll
  for (int i = 0; i < 8; i++) acc2[i] = 0ULL;
#pragma unroll 2
  for (int kp = 0; kp < NKEY; kp++){
    const ulonglong2* kk = (const ulonglong2*)kn[kp];
    ulonglong2 k0 = kk[0], k1 = kk[1], k2 = kk[2], k3 = kk[3];
    u64 da = 0ULL, db = 0ULL;
    fma2(da, qr2[0], k0.x); fma2(db, qr2[1], k0.y);
    fma2(da, qr2[2], k1.x); fma2(db, qr2[3], k1.y);
    fma2(da, qr2[4], k2.x); fma2(db, qr2[5], k2.y);
    fma2(da, qr2[6], k3.x); fma2(db, qr2[7], k3.y);
    float l = (hadd2(da) + hadd2(db)) * qs;
    float pv = __expf(l - E);
    s += pv;
    u64 pv2 = pack2(pv, pv);
    const ulonglong2* vk = (const ulonglong2*)vv[kp];
    ulonglong2 v0 = vk[0], v1 = vk[1], v2 = vk[2], v3 = vk[3];
    fma2(acc2[0], pv2, v0.x); fma2(acc2[1], pv2, v0.y);
    fma2(acc2[2], pv2, v1.x); fma2(acc2[3], pv2, v1.y);
    fma2(acc2[4], pv2, v2.x); fma2(acc2[5], pv2, v2.y);
    fma2(acc2[6], pv2, v3.x); fma2(acc2[7], pv2, v3.y);
  }
  float invs = 1.0f / s;
  float accv[HD];
#pragma unroll
  for (int i = 0; i < 8; i++) unpack2(acc2[i], accv[2*i], accv[2*i+1]);
  const ulonglong2* gw2 = (const ulonglong2*)gws;
#pragma unroll
  for (int o = 0; o < HD; o++){
    u64 a = 0ULL;
#pragma unroll
    for (int cc4 = 0; cc4 < 4; cc4++){
      ulonglong2 w = gw2[o*4 + cc4];
      fma2(a, w.x, qr2[2*cc4]); fma2(a, w.y, qr2[2*cc4+1]);
    }
    float ga = gbs[o] + hadd2(a);
    float sig = 1.0f/(1.0f + __expf(-ga));
    g_attn[(b*NCH + sc[o])*HW + pos] = accv[o]*invs*sig;
  }
}

// ---------------- MLP stage A: gate conv + exact gelu * mixed ----------------
__global__ __launch_bounds__(128) void k_mlp_gate(const float* __restrict__ wg_g,
                                                  const float* __restrict__ bg_g){
  __shared__ __align__(16) float wg[4096];
  __shared__ float bg[64];
  for (int i = threadIdx.x; i < 4096; i += 128) wg[i] = wg_g[i];
  if (threadIdx.x < 64) bg[threadIdx.x] = bg_g[threadIdx.x];
  __syncthreads();
  int p = blockIdx.x*128 + threadIdx.x;
  int b = p >> 14, pos = p & 16383;
  const float* ao = g_attn + b*NCH*HW + pos;
  const float* qk = g_qkv  + b*C3*HW + pos;
  u64 mx2[32];
#pragma unroll
  for (int c = 0; c < 64; c += 2){
    float m0 = ao[c*HW]     + qk[c*HW]     + qk[(64+c)*HW];
    float m1 = ao[(c+1)*HW] + qk[(c+1)*HW] + qk[(64+c+1)*HW];
    mx2[c>>1] = pack2(m0, m1);
  }
  float* gout = g_g + b*NCH*HW + pos;
  const ulonglong2* wg2 = (const ulonglong2*)wg;
  for (int o = 0; o < 64; o += 8){
    u64 acc[8];
#pragma unroll
    for (int i = 0; i < 8; i++) acc[i] = 0ULL;
#pragma unroll
    for (int cc4 = 0; cc4 < 16; cc4++){
      u64 x0 = mx2[2*cc4], x1 = mx2[2*cc4+1];
#pragma unroll
      for (int i = 0; i < 8; i++){
        ulonglong2 wv = wg2[(o+i)*16 + cc4];
        fma2(acc[i], wv.x, x0); fma2(acc[i], wv.y, x1);
      }
    }
#pragma unroll
    for (int i = 0; i < 8; i += 2){
      float m0, m1; unpack2(mx2[(o+i)>>1], m0, m1);
      float g0 = bg[o+i]   + hadd2(acc[i]);
      float g1 = bg[o+i+1] + hadd2(acc[i+1]);
      gout[(o+i)*HW]   = 0.5f*g0*(1.0f + erff(g0*0.70710678118f)) * m0;
      gout[(o+i+1)*HW] = 0.5f*g1*(1.0f + erff(g1*0.70710678118f)) * m1;
    }
  }
}

// ---------------- MLP stage B: down -> up(+attn residual) -> proj ----------------
__global__ __launch_bounds__(128) void k_mlp_dup(const float* __restrict__ wd_g,
    const float* __restrict__ bd_g, const float* __restrict__ wu_g,
    const float* __restrict__ bu_g, const float* __restrict__ wp_g){
  __shared__ __align__(16) float wdn[2048];
  __shared__ __align__(16) float wup[2048];
  __shared__ __align__(16) float wpj[4096];
  __shared__ float bdn[32], bup[64];
  for (int i = threadIdx.x; i < 4096; i += 128) wpj[i] = wp_g[i];
  for (int i = threadIdx.x; i < 2048; i += 128){ wdn[i] = wd_g[i]; wup[i] = wu_g[i]; }
  if (threadIdx.x < 32) bdn[threadIdx.x] = bd_g[threadIdx.x];
  if (threadIdx.x < 64) bup[threadIdx.x] = bu_g[threadIdx.x];
  __syncthreads();
  int p = blockIdx.x*128 + threadIdx.x;
  int b = p >> 14, pos = p & 16383;
  const float* gin = g_g + b*NCH*HW + pos;
  u64 g2[32];
#pragma unroll
  for (int c = 0; c < 64; c += 2)
    g2[c>>1] = pack2(gin[c*HW], gin[(c+1)*HW]);
  // down 64 -> 32
  float dvs[32];
  const ulonglong2* wd2 = (const ulonglong2*)wdn;
  for (int j = 0; j < 32; j += 4){
    u64 a0=0ULL,a1=0ULL,a2_=0ULL,a3=0ULL;
#pragma unroll
    for (int cc4 = 0; cc4 < 16; cc4++){
      u64 x0 = g2[2*cc4], x1 = g2[2*cc4+1];
      ulonglong2 w0 = wd2[(j+0)*16 + cc4];
      ulonglong2 w1 = wd2[(j+1)*16 + cc4];
      ulonglong2 w2 = wd2[(j+2)*16 + cc4];
      ulonglong2 w3 = wd2[(j+3)*16 + cc4];
      fma2(a0, w0.x, x0); fma2(a0, w0.y, x1);
      fma2(a1, w1.x, x0); fma2(a1, w1.y, x1);
      fma2(a2_, w2.x, x0); fma2(a2_, w2.y, x1);
      fma2(a3, w3.x, x0); fma2(a3, w3.y, x1);
    }
    dvs[j+0] = bdn[j+0] + hadd2(a0);
    dvs[j+1] = bdn[j+1] + hadd2(a1);
    dvs[j+2] = bdn[j+2] + hadd2(a2_);
    dvs[j+3] = bdn[j+3] + hadd2(a3);
  }
  u64 dv2[16];
#pragma unroll
  for (int j = 0; j < 32; j += 2) dv2[j>>1] = pack2(dvs[j], dvs[j+1]);
  // up 32 -> 64 + attn residual
  const float* ao = g_attn + b*NCH*HW + pos;
  u64 o22[32];
  const ulonglong2* wu2 = (const ulonglong2*)wup;
  for (int o = 0; o < 64; o += 8){
    u64 acc[8];
#pragma unroll
    for (int i = 0; i < 8; i++) acc[i] = 0ULL;
#pragma unroll
    for (int jj4 = 0; jj4 < 8; jj4++){
      u64 x0 = dv2[2*jj4], x1 = dv2[2*jj4+1];
#pragma unroll
      for (int i = 0; i < 8; i++){
        ulonglong2 wv = wu2[(o+i)*8 + jj4];
        fma2(acc[i], wv.x, x0); fma2(acc[i], wv.y, x1);
      }
    }
#pragma unroll
    for (int i = 0; i < 8; i += 2)
      o22[(o+i)>>1] = pack2(ao[(o+i)*HW]   + bup[o+i]   + hadd2(acc[i]),
                            ao[(o+i+1)*HW] + bup[o+i+1] + hadd2(acc[i+1]));
  }
  // proj 64 -> 64
  float* outp = g_out3 + b*NCH*HW + pos;
  const ulonglong2* wp2 = (const ulonglong2*)wpj;
  for (int o = 0; o < 64; o += 8){
    u64 acc[8];
#pragma unroll
    for (int i = 0; i < 8; i++) acc[i] = 0ULL;
#pragma unroll
    for (int cc4 = 0; cc4 < 16; cc4++){
      u64 x0 = o22[2*cc4], x1 = o22[2*cc4+1];
#pragma unroll
      for (int i = 0; i < 8; i++){
        ulonglong2 wv = wp2[(o+i)*16 + cc4];
        fma2(acc[i], wv.x, x0); fma2(acc[i], wv.y, x1);
      }
    }
#pragma unroll
    for (int i = 0; i < 8; i++) outp[(o+i)*HW] = hadd2(acc[i]);
  }
}

// ---------------- depthwise 3x3 reflect + bias, 4 px/thread ----------------
__global__ __launch_bounds__(256) void k_lp(const float* __restrict__ wl,
                                            const float* __restrict__ bl){
  int t = blockIdx.x*256 + threadIdx.x;
  int base = t*4;
  int w4 = base & 127, h = (base>>7)&127, bc = base>>14;
  int ch = bc & 63;
  const float* src = g_out3 + bc*HW;
  const float* kk = wl + ch*9;
  float bv = bl[ch];
  float o0=bv,o1=bv,o2=bv,o3=bv;
#pragma unroll
  for (int dy = 0; dy < 3; dy++){
    int ih = h + dy - 1;
    ih = (ih < 0) ? -ih : ((ih > 127) ? 254-ih : ih);
    const float* r = src + ih*128 + w4;
    float4 m = *(const float4*)r;
    float lf = (w4 > 0)   ? r[-1] : r[1];
    float rt = (w4 < 124) ? r[4]  : r[2];
    float ka = kk[dy*3], kb = kk[dy*3+1], kc = kk[dy*3+2];
    o0 = fmaf(lf,ka,fmaf(m.x,kb,fmaf(m.y,kc,o0)));
    o1 = fmaf(m.x,ka,fmaf(m.y,kb,fmaf(m.z,kc,o1)));
    o2 = fmaf(m.y,ka,fmaf(m.z,kb,fmaf(m.w,kc,o2)));
    o3 = fmaf(m.z,ka,fmaf(m.w,kb,fmaf(rt,kc,o3)));
  }
  *(float4*)(g_lp + base) = make_float4(o0,o1,o2,o3);
}

// ---------------- bilinear x2 upsample, align_corners, 2 px/thread ----------------
__global__ __launch_bounds__(256) void k_up(float* __restrict__ outp){
  int t = blockIdx.x*256 + threadIdx.x;
  int ix = t*2;                              // 16777216 outputs
  int X = ix & 255, Y = (ix>>8)&255, bc = ix>>16;
  float cy = Y * (127.0f/255.0f);
  int y0 = (int)cy; if (y0 > 126) y0 = 126;
  float wy = cy - (float)y0;
  const float* tr = g_lp + bc*HW + y0*128;
  float2 res;
#pragma unroll
  for (int i = 0; i < 2; i++){
    float cx = (X+i) * (127.0f/255.0f);
    int x0 = (int)cx; if (x0 > 126) x0 = 126;
    float wx = cx - (float)x0;
    float v00 = tr[x0],       v01 = tr[x0+1];
    float v10 = tr[128+x0],   v11 = tr[128+x0+1];
    float u0 = v00 + (v10 - v00)*wy;
    float u1 = v01 + (v11 - v01)*wy;
    ((float*)&res)[i] = u0 + (u1 - u0)*wx;
  }
  *(float2*)(outp + ix) = res;
}

// ---------------- launch ----------------
extern "C" void kernel_launch(void* const* d_in, const int* in_sizes, int n_in,
                              void* d_out, int out_size){
  const float* x     = (const float*)d_in[0];
  const float* qkvw  = (const float*)d_in[1];
  const float* lcew  = (const float*)d_in[2];
  const float* gatew = (const float*)d_in[3];
  const float* gateb = (const float*)d_in[4];
  const float* temp  = (const float*)d_in[5];
  const float* relh  = (const float*)d_in[6];
  const float* relw  = (const float*)d_in[7];
  const float* downw = (const float*)d_in[8];
  const float* downb = (const float*)d_in[9];
  const float* upw   = (const float*)d_in[10];
  const float* upb   = (const float*)d_in[11];
  const float* gatingw = (const float*)d_in[12];
  const float* gatingb = (const float*)d_in[13];
  const float* projw = (const float*)d_in[14];
  const float* lpw   = (const float*)d_in[15];
  const float* lpb   = (const float*)d_in[16];
  float* outp = (float*)d_out;

  k_pool_qkv<<<512, 128>>>(x, qkvw);
  k_dw3<<<(BATCH*C3*HW)/1024, 256>>>(lcew);
  k_gram<<<dim3(128, BATCH), 256>>>();
  k_stats<<<BATCH, 256>>>();
  k_attn<<<dim3(256, NHEADS, BATCH), 64>>>(gatew, gateb, temp, relh, relw);
  k_mlp_gate<<<512, 128>>>(gatingw, gatingb);
  k_mlp_dup<<<512, 128>>>(downw, downb, upw, upb, projw);
  k_lp<<<(BATCH*NCH*HW)/1024, 256>>>(lpw, lpb);
  k_up<<<(BATCH*NCH*65536)/512, 256>>>(outp);
}

// round 4
// speedup vs baseline: 1.2538x; 1.1227x over previous
#include <cuda_runtime.h>
#include <math.h>

#define BATCH 4
#define HW 16384
#define NCH 64
#define C3 192
#define NHEADS 4
#define HD 16
#define NKEY 100

typedef unsigned long long u64;

// ---------------- f32x2 packed-math helpers (sm_100+) ----------------
__device__ __forceinline__ u64 pack2(float a, float b){
  u64 r; asm("mov.b64 %0, {%1, %2};" : "=l"(r) : "f"(a), "f"(b)); return r;
}
__device__ __forceinline__ void fma2(u64 &d, u64 a, u64 b){
  asm("fma.rn.f32x2 %0, %1, %2, %0;" : "+l"(d) : "l"(a), "l"(b));
}
__device__ __forceinline__ void unpack2(u64 a, float &x, float &y){
  asm("mov.b64 {%0, %1}, %2;" : "=f"(x), "=f"(y) : "l"(a));
}
__device__ __forceinline__ float hadd2(u64 a){
  float x, y; unpack2(a, x, y); return x + y;
}
union F4U { float4 f; ulonglong2 u; };

// ---------------- scratch ----------------
__device__ __align__(16) float g_y1[BATCH*C3*HW];
__device__ __align__(16) float g_qkv[BATCH*C3*HW];
__device__ __align__(16) float g_attn[BATCH*NCH*HW];
__device__ __align__(16) float g_out3[BATCH*NCH*HW];
__device__ __align__(16) float g_lp[BATCH*NCH*HW];
__device__ __align__(16) float g_g[BATCH*NCH*HW];
__device__ float g_Sp[BATCH*128*NCH];
__device__ __align__(16) float g_Gpart[BATCH*128*NCH*NCH];
__device__ __align__(16) float g_G[BATCH*NCH*NCH];       // reduced Gram
__device__ float g_S[BATCH*NCH];                          // reduced sums
__device__ int   g_idx[BATCH*NCH];

// ---------------- fused maxpool2 + conv1x1 (64 -> 192), 1 px/thread ----------------
__global__ __launch_bounds__(128) void k_pool_qkv(const float* __restrict__ x,
                                                  const float* __restrict__ wq){
  __shared__ __align__(16) float ws[C3*NCH];                 // 48KB
  for (int i = threadIdx.x; i < C3*NCH; i += 128) ws[i] = wq[i];
  __syncthreads();
  int p = blockIdx.x*128 + threadIdx.x;        // 65536 pixels
  int b = p >> 14, rem = p & 16383;
  int h = rem >> 7, w = rem & 127;
  const float* xb = x + b*NCH*65536 + (h*2)*256 + (w*2);
  u64 a2[32];
#pragma unroll
  for (int c = 0; c < NCH; c += 2){
    const float* xc0 = xb + c*65536;
    float2 f0 = *(const float2*)xc0;
    float2 f1 = *(const float2*)(xc0 + 256);
    float p0 = fmaxf(fmaxf(f0.x, f0.y), fmaxf(f1.x, f1.y));
    const float* xc1 = xc0 + 65536;
    float2 g0 = *(const float2*)xc1;
    float2 g1 = *(const float2*)(xc1 + 256);
    float p1 = fmaxf(fmaxf(g0.x, g0.y), fmaxf(g1.x, g1.y));
    a2[c>>1] = pack2(p0, p1);
  }
  float* outp = g_y1 + b*C3*HW + rem;
  const ulonglong2* wsu = (const ulonglong2*)ws;
  for (int o = 0; o < C3; o += 8){
    u64 acc[8];
#pragma unroll
    for (int i = 0; i < 8; i++) acc[i] = 0ULL;
#pragma unroll
    for (int cc4 = 0; cc4 < 16; cc4++){
      u64 x0 = a2[2*cc4], x1 = a2[2*cc4+1];
#pragma unroll
      for (int i = 0; i < 8; i++){
        ulonglong2 wv = wsu[(o+i)*16 + cc4];
        fma2(acc[i], wv.x, x0); fma2(acc[i], wv.y, x1);
      }
    }
#pragma unroll
    for (int i = 0; i < 8; i++) outp[(o+i)*HW] = hadd2(acc[i]);
  }
}

// ---------------- depthwise 3x3 zero pad, 4 px/thread ----------------
__global__ __launch_bounds__(256) void k_dw3(const float* __restrict__ wd){
  int t = blockIdx.x*256 + threadIdx.x;
  int base = t*4;
  int w4 = base & 127, h = (base>>7)&127, bc = base>>14;
  int ch = bc % C3;
  const float* src = g_y1 + bc*HW;
  const float* kk = wd + ch*9;
  float o0=0.f,o1=0.f,o2=0.f,o3=0.f;
#pragma unroll
  for (int dy = 0; dy < 3; dy++){
    int ih = h + dy - 1;
    if ((unsigned)ih >= 128u) continue;
    const float* r = src + ih*128 + w4;
    float4 m = *(const float4*)r;
    float lf = (w4 > 0)   ? r[-1] : 0.f;
    float rt = (w4 < 124) ? r[4]  : 0.f;
    float ka = kk[dy*3], kb = kk[dy*3+1], kc = kk[dy*3+2];
    o0 = fmaf(lf,ka,fmaf(m.x,kb,fmaf(m.y,kc,o0)));
    o1 = fmaf(m.x,ka,fmaf(m.y,kb,fmaf(m.z,kc,o1)));
    o2 = fmaf(m.y,ka,fmaf(m.z,kb,fmaf(m.w,kc,o2)));
    o3 = fmaf(m.z,ka,fmaf(m.w,kb,fmaf(rt,kc,o3)));
  }
  *(float4*)(g_qkv + base) = make_float4(o0,o1,o2,o3);
}

// ---------------- Gram partials + per-slice channel sums ----------------
__global__ __launch_bounds__(256) void k_gram(){
  __shared__ __align__(16) float sh[64*128];
  int b = blockIdx.y, sp = blockIdx.x;
  int tid = threadIdx.x;
  int tc = (tid >> 4) << 2;
  int td = (tid & 15) << 2;
  const float* qb = g_qkv + b*C3*HW + sp*128;
  float4* sh4 = (float4*)sh;
  for (int i = tid; i < 2048; i += 256){
    int c = i >> 5, nn4 = i & 31;
    sh4[c*32 + (nn4 ^ (c>>2))] = *(const float4*)(qb + c*HW + nn4*4);
  }
  __syncthreads();
  u64 acc[4][4];
#pragma unroll
  for (int i = 0; i < 4; i++)
#pragma unroll
    for (int j = 0; j < 4; j++) acc[i][j] = 0ULL;
  const F4U* shf = (const F4U*)sh;
  for (int nn4 = 0; nn4 < 32; nn4++){
    F4U av[4], bv[4];
#pragma unroll
    for (int i = 0; i < 4; i++){ int r = tc + i; av[i] = shf[r*32 + (nn4 ^ (r>>2))]; }
#pragma unroll
    for (int j = 0; j < 4; j++){ int r = td + j; bv[j] = shf[r*32 + (nn4 ^ (r>>2))]; }
#pragma unroll
    for (int i = 0; i < 4; i++)
#pragma unroll
      for (int j = 0; j < 4; j++){
        fma2(acc[i][j], av[i].u.x, bv[j].u.x);
        fma2(acc[i][j], av[i].u.y, bv[j].u.y);
      }
  }
#pragma unroll
  for (int i = 0; i < 4; i++)
#pragma unroll
    for (int j = 0; j < 4; j++)
      g_Gpart[((b*128+sp)*64 + tc+i)*64 + td+j] = hadd2(acc[i][j]);
  if (tid < 64){
    float s = 0.f;
    for (int nn4 = 0; nn4 < 32; nn4++){
      F4U f = shf[tid*32 + (nn4 ^ (tid>>2))];
      s += (f.f.x + f.f.y) + (f.f.z + f.f.w);
    }
    g_Sp[(b*128+sp)*64 + tid] = s;
  }
}

// ---------------- chip-wide reduction of Gram partials + channel sums ----------------
__global__ __launch_bounds__(256) void k_reduce(){
  int t = blockIdx.x*256 + threadIdx.x;      // 16384 threads: (b, cd)
  int b = t >> 12, cd = t & 4095;
  const float* src = g_Gpart + (size_t)b*128*4096 + cd;
  float s = 0.f;
#pragma unroll 8
  for (int sp = 0; sp < 128; sp++) s += src[sp*4096];
  g_G[b*4096 + cd] = s;
  if (cd < 64){
    const float* sq = g_Sp + b*128*64 + cd;
    float ss = 0.f;
#pragma unroll 8
    for (int sp = 0; sp < 128; sp++) ss += sq[sp*64];
    g_S[b*64 + cd] = ss;
  }
}

// ---------------- cov -> sim -> stable ranking (tiny now) ----------------
__global__ void k_stats(){
  __shared__ float covs[64][64];
  __shared__ float stds[64];
  __shared__ float sims[64];
  __shared__ float shS[64];
  int b = blockIdx.x;
  if (threadIdx.x < 64) shS[threadIdx.x] = g_S[b*64 + threadIdx.x];
  __syncthreads();
  for (int pr = threadIdx.x; pr < 4096; pr += 256){
    int c = pr>>6, d = pr&63;
    covs[c][d] = g_G[b*4096 + pr] - shS[c]*shS[d]*(1.0f/16384.0f);
  }
  __syncthreads();
  if (threadIdx.x < 64)
    stds[threadIdx.x] = sqrtf(covs[threadIdx.x][threadIdx.x] + 1e-8f);
  __syncthreads();
  if (threadIdx.x < 64){
    int c = threadIdx.x;
    float sc = stds[c], a = 0.f;
    for (int d = 0; d < 64; d++) a += covs[c][d] / fmaxf(sc*stds[d], 1e-8f);
    sims[c] = a * (1.0f/64.0f);
  }
  __syncthreads();
  if (threadIdx.x < 64){
    int c = threadIdx.x;
    float v = sims[c]; int r = 0;
    for (int d = 0; d < 64; d++){
      float u = sims[d];
      r += (u > v) || (u == v && d < c);
    }
    g_idx[b*64 + r] = c;
  }
}

// ---------------- block-local halo attention + gate + scatter ----------------
__global__ __launch_bounds__(64) void k_attn(const float* __restrict__ gatew,
    const float* __restrict__ gateb, const float* __restrict__ temp,
    const float* __restrict__ relh, const float* __restrict__ relw){
  __shared__ int   sc[HD];
  __shared__ __align__(16) float kn[NKEY][HD];
  __shared__ __align__(16) float vv[NKEY][HD];
  __shared__ __align__(16) float gws[HD*HD];
  __shared__ float gbs[HD];
  int tid = threadIdx.x;
  int g = blockIdx.y, b = blockIdx.z;
  if (tid < HD){
    sc[tid]  = g_idx[b*64 + g*HD + tid];
    gbs[tid] = gateb[g*HD + tid];
  }
  for (int i = tid; i < HD*HD; i += 64) gws[i] = gatew[g*HD*HD + i];
  __syncthreads();
  int bh = blockIdx.x >> 4, bw = blockIdx.x & 15;
  int h0 = bh*8, w0 = bw*8;
  for (int p = tid; p < NKEY; p += 64){
    int ry = p/10, rx = p - ry*10;
    int gh = h0 - 1 + ry, gw2 = w0 - 1 + rx;
    bool inb = ((unsigned)gh < 128u) && ((unsigned)gw2 < 128u);
    int posk = gh*128 + gw2;
    float ss = 0.f; float tmp[HD];
#pragma unroll
    for (int c = 0; c < HD; c++){
      float base = 0.f, vval = 0.f;
      if (inb){
        int off = (b*C3 + sc[c])*HW + posk;
        base = g_qkv[off + 64*HW];
        vval = g_qkv[off + 128*HW];
      }
      float rel = (c < 8) ? relh[(g*10+ry)*8 + c] : relw[(g*10+rx)*8 + (c-8)];
      float kv = base + rel;
      tmp[c] = kv; ss += kv*kv;
      vv[p][c] = vval;
    }
    float inv = 1.0f / fmaxf(sqrtf(ss), 1e-12f);
#pragma unroll
    for (int c = 0; c < HD; c++) kn[p][c] = tmp[c]*inv;
  }
  int qy = tid >> 3, qx = tid & 7;
  int pos = (h0+qy)*128 + (w0+qx);
  float qraw[HD]; float ss = 0.f;
#pragma unroll
  for (int c = 0; c < HD; c++){
    float v = g_qkv[(b*C3 + sc[c])*HW + pos];
    qraw[c] = v; ss += v*v;
  }
  u64 qr2[8];
#pragma unroll
  for (int c = 0; c < HD; c += 2) qr2[c>>1] = pack2(qraw[c], qraw[c+1]);
  float E  = __expf(temp[g]);
  float qs = E / fmaxf(sqrtf(ss), 1e-12f);
  __syncthreads();
  float s = 0.f;
  u64 acc2[8];
#pragma unroll
  for (int i = 0; i < 8; i++) acc2[i] = 0ULL;
#pragma unroll 2
  for (int kp = 0; kp < NKEY; kp++){
    const ulonglong2* kk = (const ulonglong2*)kn[kp];
    ulonglong2 k0 = kk[0], k1 = kk[1], k2 = kk[2], k3 = kk[3];
    u64 da = 0ULL, db = 0ULL;
    fma2(da, qr2[0], k0.x); fma2(db, qr2[1], k0.y);
    fma2(da, qr2[2], k1.x); fma2(db, qr2[3], k1.y);
    fma2(da, qr2[4], k2.x); fma2(db, qr2[5], k2.y);
    fma2(da, qr2[6], k3.x); fma2(db, qr2[7], k3.y);
    float l = (hadd2(da) + hadd2(db)) * qs;
    float pv = __expf(l - E);
    s += pv;
    u64 pv2 = pack2(pv, pv);
    const ulonglong2* vk = (const ulonglong2*)vv[kp];
    ulonglong2 v0 = vk[0], v1 = vk[1], v2 = vk[2], v3 = vk[3];
    fma2(acc2[0], pv2, v0.x); fma2(acc2[1], pv2, v0.y);
    fma2(acc2[2], pv2, v1.x); fma2(acc2[3], pv2, v1.y);
    fma2(acc2[4], pv2, v2.x); fma2(acc2[5], pv2, v2.y);
    fma2(acc2[6], pv2, v3.x); fma2(acc2[7], pv2, v3.y);
  }
  float invs = 1.0f / s;
  float accv[HD];
#pragma unroll
  for (int i = 0; i < 8; i++) unpack2(acc2[i], accv[2*i], accv[2*i+1]);
  const ulonglong2* gw2 = (const ulonglong2*)gws;
#pragma unroll
  for (int o = 0; o < HD; o++){
    u64 a = 0ULL;
#pragma unroll
    for (int cc4 = 0; cc4 < 4; cc4++){
      ulonglong2 w = gw2[o*4 + cc4];
      fma2(a, w.x, qr2[2*cc4]); fma2(a, w.y, qr2[2*cc4+1]);
    }
    float ga = gbs[o] + hadd2(a);
    float sig = 1.0f/(1.0f + __expf(-ga));
    g_attn[(b*NCH + sc[o])*HW + pos] = accv[o]*invs*sig;
  }
}

// ---------------- MLP stage A: gate conv + exact gelu * mixed ----------------
__global__ __launch_bounds__(128) void k_mlp_gate(const float* __restrict__ wg_g,
                                                  const float* __restrict__ bg_g){
  __shared__ __align__(16) float wg[4096];
  __shared__ float bg[64];
  for (int i = threadIdx.x; i < 4096; i += 128) wg[i] = wg_g[i];
  if (threadIdx.x < 64) bg[threadIdx.x] = bg_g[threadIdx.x];
  __syncthreads();
  int p = blockIdx.x*128 + threadIdx.x;
  int b = p >> 14, pos = p & 16383;
  const float* ao = g_attn + b*NCH*HW + pos;
  const float* qk = g_qkv  + b*C3*HW + pos;
  u64 mx2[32];
#pragma unroll
  for (int c = 0; c < 64; c += 2){
    float m0 = ao[c*HW]     + qk[c*HW]     + qk[(64+c)*HW];
    float m1 = ao[(c+1)*HW] + qk[(c+1)*HW] + qk[(64+c+1)*HW];
    mx2[c>>1] = pack2(m0, m1);
  }
  float* gout = g_g + b*NCH*HW + pos;
  const ulonglong2* wg2 = (const ulonglong2*)wg;
  for (int o = 0; o < 64; o += 8){
    u64 acc[8];
#pragma unroll
    for (int i = 0; i < 8; i++) acc[i] = 0ULL;
#pragma unroll
    for (int cc4 = 0; cc4 < 16; cc4++){
      u64 x0 = mx2[2*cc4], x1 = mx2[2*cc4+1];
#pragma unroll
      for (int i = 0; i < 8; i++){
        ulonglong2 wv = wg2[(o+i)*16 + cc4];
        fma2(acc[i], wv.x, x0); fma2(acc[i], wv.y, x1);
      }
    }
#pragma unroll
    for (int i = 0; i < 8; i += 2){
      float m0, m1; unpack2(mx2[(o+i)>>1], m0, m1);
      float g0 = bg[o+i]   + hadd2(acc[i]);
      float g1 = bg[o+i+1] + hadd2(acc[i+1]);
      gout[(o+i)*HW]   = 0.5f*g0*(1.0f + erff(g0*0.70710678118f)) * m0;
      gout[(o+i+1)*HW] = 0.5f*g1*(1.0f + erff(g1*0.70710678118f)) * m1;
    }
  }
}

// ---------------- MLP stage B: down -> up(+attn residual) -> proj ----------------
__global__ __launch_bounds__(128) void k_mlp_dup(const float* __restrict__ wd_g,
    const float* __restrict__ bd_g, const float* __restrict__ wu_g,
    const float* __restrict__ bu_g, const float* __restrict__ wp_g){
  __shared__ __align__(16) float wdn[2048];
  __shared__ __align__(16) float wup[2048];
  __shared__ __align__(16) float wpj[4096];
  __shared__ float bdn[32], bup[64];
  for (int i = threadIdx.x; i < 4096; i += 128) wpj[i] = wp_g[i];
  for (int i = threadIdx.x; i < 2048; i += 128){ wdn[i] = wd_g[i]; wup[i] = wu_g[i]; }
  if (threadIdx.x < 32) bdn[threadIdx.x] = bd_g[threadIdx.x];
  if (threadIdx.x < 64) bup[threadIdx.x] = bu_g[threadIdx.x];
  __syncthreads();
  int p = blockIdx.x*128 + threadIdx.x;
  int b = p >> 14, pos = p & 16383;
  const float* gin = g_g + b*NCH*HW + pos;
  u64 g2[32];
#pragma unroll
  for (int c = 0; c < 64; c += 2)
    g2[c>>1] = pack2(gin[c*HW], gin[(c+1)*HW]);
  float dvs[32];
  const ulonglong2* wd2 = (const ulonglong2*)wdn;
  for (int j = 0; j < 32; j += 4){
    u64 a0=0ULL,a1=0ULL,a2_=0ULL,a3=0ULL;
#pragma unroll
    for (int cc4 = 0; cc4 < 16; cc4++){
      u64 x0 = g2[2*cc4], x1 = g2[2*cc4+1];
      ulonglong2 w0 = wd2[(j+0)*16 + cc4];
      ulonglong2 w1 = wd2[(j+1)*16 + cc4];
      ulonglong2 w2 = wd2[(j+2)*16 + cc4];
      ulonglong2 w3 = wd2[(j+3)*16 + cc4];
      fma2(a0, w0.x, x0); fma2(a0, w0.y, x1);
      fma2(a1, w1.x, x0); fma2(a1, w1.y, x1);
      fma2(a2_, w2.x, x0); fma2(a2_, w2.y, x1);
      fma2(a3, w3.x, x0); fma2(a3, w3.y, x1);
    }
    dvs[j+0] = bdn[j+0] + hadd2(a0);
    dvs[j+1] = bdn[j+1] + hadd2(a1);
    dvs[j+2] = bdn[j+2] + hadd2(a2_);
    dvs[j+3] = bdn[j+3] + hadd2(a3);
  }
  u64 dv2[16];
#pragma unroll
  for (int j = 0; j < 32; j += 2) dv2[j>>1] = pack2(dvs[j], dvs[j+1]);
  const float* ao = g_attn + b*NCH*HW + pos;
  u64 o22[32];
  const ulonglong2* wu2 = (const ulonglong2*)wup;
  for (int o = 0; o < 64; o += 8){
    u64 acc[8];
#pragma unroll
    for (int i = 0; i < 8; i++) acc[i] = 0ULL;
#pragma unroll
    for (int jj4 = 0; jj4 < 8; jj4++){
      u64 x0 = dv2[2*jj4], x1 = dv2[2*jj4+1];
#pragma unroll
      for (int i = 0; i < 8; i++){
        ulonglong2 wv = wu2[(o+i)*8 + jj4];
        fma2(acc[i], wv.x, x0); fma2(acc[i], wv.y, x1);
      }
    }
#pragma unroll
    for (int i = 0; i < 8; i += 2)
      o22[(o+i)>>1] = pack2(ao[(o+i)*HW]   + bup[o+i]   + hadd2(acc[i]),
                            ao[(o+i+1)*HW] + bup[o+i+1] + hadd2(acc[i+1]));
  }
  float* outp = g_out3 + b*NCH*HW + pos;
  const ulonglong2* wp2 = (const ulonglong2*)wpj;
  for (int o = 0; o < 64; o += 8){
    u64 acc[8];
#pragma unroll
    for (int i = 0; i < 8; i++) acc[i] = 0ULL;
#pragma unroll
    for (int cc4 = 0; cc4 < 16; cc4++){
      u64 x0 = o22[2*cc4], x1 = o22[2*cc4+1];
#pragma unroll
      for (int i = 0; i < 8; i++){
        ulonglong2 wv = wp2[(o+i)*16 + cc4];
        fma2(acc[i], wv.x, x0); fma2(acc[i], wv.y, x1);
      }
    }
#pragma unroll
    for (int i = 0; i < 8; i++) outp[(o+i)*HW] = hadd2(acc[i]);
  }
}

// ---------------- depthwise 3x3 reflect + bias, 4 px/thread ----------------
__global__ __launch_bounds__(256) void k_lp(const float* __restrict__ wl,
                                            const float* __restrict__ bl){
  int t = blockIdx.x*256 + threadIdx.x;
  int base = t*4;
  int w4 = base & 127, h = (base>>7)&127, bc = base>>14;
  int ch = bc & 63;
  const float* src = g_out3 + bc*HW;
  const float* kk = wl + ch*9;
  float bv = bl[ch];
  float o0=bv,o1=bv,o2=bv,o3=bv;
#pragma unroll
  for (int dy = 0; dy < 3; dy++){
    int ih = h + dy - 1;
    ih = (ih < 0) ? -ih : ((ih > 127) ? 254-ih : ih);
    const float* r = src + ih*128 + w4;
    float4 m = *(const float4*)r;
    float lf = (w4 > 0)   ? r[-1] : r[1];
    float rt = (w4 < 124) ? r[4]  : r[2];
    float ka = kk[dy*3], kb = kk[dy*3+1], kc = kk[dy*3+2];
    o0 = fmaf(lf,ka,fmaf(m.x,kb,fmaf(m.y,kc,o0)));
    o1 = fmaf(m.x,ka,fmaf(m.y,kb,fmaf(m.z,kc,o1)));
    o2 = fmaf(m.y,ka,fmaf(m.z,kb,fmaf(m.w,kc,o2)));
    o3 = fmaf(m.z,ka,fmaf(m.w,kb,fmaf(rt,kc,o3)));
  }
  *(float4*)(g_lp + base) = make_float4(o0,o1,o2,o3);
}

// ---------------- bilinear x2 upsample, align_corners, 2 px/thread ----------------
__global__ __launch_bounds__(256) void k_up(float* __restrict__ outp){
  int t = blockIdx.x*256 + threadIdx.x;
  int ix = t*2;
  int X = ix & 255, Y = (ix>>8)&255, bc = ix>>16;
  float cy = Y * (127.0f/255.0f);
  int y0 = (int)cy; if (y0 > 126) y0 = 126;
  float wy = cy - (float)y0;
  const float* tr = g_lp + bc*HW + y0*128;
  float2 res;
#pragma unroll
  for (int i = 0; i < 2; i++){
    float cx = (X+i) * (127.0f/255.0f);
    int x0 = (int)cx; if (x0 > 126) x0 = 126;
    float wx = cx - (float)x0;
    float v00 = tr[x0],       v01 = tr[x0+1];
    float v10 = tr[128+x0],   v11 = tr[128+x0+1];
    float u0 = v00 + (v10 - v00)*wy;
    float u1 = v01 + (v11 - v01)*wy;
    ((float*)&res)[i] = u0 + (u1 - u0)*wx;
  }
  *(float2*)(outp + ix) = res;
}

// ---------------- launch ----------------
extern "C" void kernel_launch(void* const* d_in, const int* in_sizes, int n_in,
                              void* d_out, int out_size){
  const float* x     = (const float*)d_in[0];
  const float* qkvw  = (const float*)d_in[1];
  const float* lcew  = (const float*)d_in[2];
  const float* gatew = (const float*)d_in[3];
  const float* gateb = (const float*)d_in[4];
  const float* temp  = (const float*)d_in[5];
  const float* relh  = (const float*)d_in[6];
  const float* relw  = (const float*)d_in[7];
  const float* downw = (const float*)d_in[8];
  const float* downb = (const float*)d_in[9];
  const float* upw   = (const float*)d_in[10];
  const float* upb   = (const float*)d_in[11];
  const float* gatingw = (const float*)d_in[12];
  const float* gatingb = (const float*)d_in[13];
  const float* projw = (const float*)d_in[14];
  const float* lpw   = (const float*)d_in[15];
  const float* lpb   = (const float*)d_in[16];
  float* outp = (float*)d_out;

  k_pool_qkv<<<512, 128>>>(x, qkvw);
  k_dw3<<<(BATCH*C3*HW)/1024, 256>>>(lcew);
  k_gram<<<dim3(128, BATCH), 256>>>();
  k_reduce<<<64, 256>>>();
  k_stats<<<BATCH, 256>>>();
  k_attn<<<dim3(256, NHEADS, BATCH), 64>>>(gatew, gateb, temp, relh, relw);
  k_mlp_gate<<<512, 128>>>(gatingw, gatingb);
  k_mlp_dup<<<512, 128>>>(downw, downb, upw, upb, projw);
  k_lp<<<(BATCH*NCH*HW)/1024, 256>>>(lpw, lpb);
  k_up<<<(BATCH*NCH*65536)/512, 256>>>(outp);
}

// round 5
// speedup vs baseline: 1.2635x; 1.0077x over previous
#include <cuda_runtime.h>
#include <math.h>

#define BATCH 4
#define HW 16384
#define NCH 64
#define C3 192
#define NHEADS 4
#define HD 16
#define NKEY 100

typedef unsigned long long u64;

// ---------------- f32x2 packed-math helpers (sm_100+) ----------------
__device__ __forceinline__ u64 pack2(float a, float b){
  u64 r; asm("mov.b64 %0, {%1, %2};" : "=l"(r) : "f"(a), "f"(b)); return r;
}
__device__ __forceinline__ void fma2(u64 &d, u64 a, u64 b){
  asm("fma.rn.f32x2 %0, %1, %2, %0;" : "+l"(d) : "l"(a), "l"(b));
}
__device__ __forceinline__ void unpack2(u64 a, float &x, float &y){
  asm("mov.b64 {%0, %1}, %2;" : "=f"(x), "=f"(y) : "l"(a));
}
__device__ __forceinline__ float hadd2(u64 a){
  float x, y; unpack2(a, x, y); return x + y;
}
union F4U { float4 f; ulonglong2 u; };

// ---------------- scratch ----------------
__device__ __align__(16) float g_y1[BATCH*C3*HW];
__device__ __align__(16) float g_qkv[BATCH*C3*HW];
__device__ __align__(16) float g_attn[BATCH*NCH*HW];
__device__ __align__(16) float g_out3[BATCH*NCH*HW];
__device__ __align__(16) float g_lp[BATCH*NCH*HW];
__device__ __align__(16) float g_g[BATCH*NCH*HW];
__device__ float g_Sp[BATCH*128*NCH];
__device__ __align__(16) float g_Gpart[BATCH*128*NCH*NCH];
__device__ __align__(16) float g_Gred[8*BATCH*NCH*NCH];   // 8 chunk-partials
__device__ float g_S[BATCH*NCH];
__device__ int   g_idx[BATCH*NCH];

// ---------------- fused maxpool2 + conv1x1 (64 -> 192), 1 px/thread ----------------
__global__ __launch_bounds__(128) void k_pool_qkv(const float* __restrict__ x,
                                                  const float* __restrict__ wq){
  __shared__ __align__(16) float ws[C3*NCH];                 // 48KB
  for (int i = threadIdx.x; i < C3*NCH; i += 128) ws[i] = wq[i];
  __syncthreads();
  int p = blockIdx.x*128 + threadIdx.x;        // 65536 pixels
  int b = p >> 14, rem = p & 16383;
  int h = rem >> 7, w = rem & 127;
  const float* xb = x + b*NCH*65536 + (h*2)*256 + (w*2);
  u64 a2[32];
#pragma unroll
  for (int c = 0; c < NCH; c += 2){
    const float* xc0 = xb + c*65536;
    float2 f0 = *(const float2*)xc0;
    float2 f1 = *(const float2*)(xc0 + 256);
    float p0 = fmaxf(fmaxf(f0.x, f0.y), fmaxf(f1.x, f1.y));
    const float* xc1 = xc0 + 65536;
    float2 g0 = *(const float2*)xc1;
    float2 g1 = *(const float2*)(xc1 + 256);
    float p1 = fmaxf(fmaxf(g0.x, g0.y), fmaxf(g1.x, g1.y));
    a2[c>>1] = pack2(p0, p1);
  }
  float* outp = g_y1 + b*C3*HW + rem;
  const ulonglong2* wsu = (const ulonglong2*)ws;
  for (int o = 0; o < C3; o += 8){
    u64 acc[8];
#pragma unroll
    for (int i = 0; i < 8; i++) acc[i] = 0ULL;
#pragma unroll
    for (int cc4 = 0; cc4 < 16; cc4++){
      u64 x0 = a2[2*cc4], x1 = a2[2*cc4+1];
#pragma unroll
      for (int i = 0; i < 8; i++){
        ulonglong2 wv = wsu[(o+i)*16 + cc4];
        fma2(acc[i], wv.x, x0); fma2(acc[i], wv.y, x1);
      }
    }
#pragma unroll
    for (int i = 0; i < 8; i++) outp[(o+i)*HW] = hadd2(acc[i]);
  }
}

// ---------------- depthwise 3x3 zero pad, 4 px/thread ----------------
__global__ __launch_bounds__(256) void k_dw3(const float* __restrict__ wd){
  int t = blockIdx.x*256 + threadIdx.x;
  int base = t*4;
  int w4 = base & 127, h = (base>>7)&127, bc = base>>14;
  int ch = bc % C3;
  const float* src = g_y1 + bc*HW;
  const float* kk = wd + ch*9;
  float o0=0.f,o1=0.f,o2=0.f,o3=0.f;
#pragma unroll
  for (int dy = 0; dy < 3; dy++){
    int ih = h + dy - 1;
    if ((unsigned)ih >= 128u) continue;
    const float* r = src + ih*128 + w4;
    float4 m = *(const float4*)r;
    float lf = (w4 > 0)   ? r[-1] : 0.f;
    float rt = (w4 < 124) ? r[4]  : 0.f;
    float ka = kk[dy*3], kb = kk[dy*3+1], kc = kk[dy*3+2];
    o0 = fmaf(lf,ka,fmaf(m.x,kb,fmaf(m.y,kc,o0)));
    o1 = fmaf(m.x,ka,fmaf(m.y,kb,fmaf(m.z,kc,o1)));
    o2 = fmaf(m.y,ka,fmaf(m.z,kb,fmaf(m.w,kc,o2)));
    o3 = fmaf(m.z,ka,fmaf(m.w,kb,fmaf(rt,kc,o3)));
  }
  *(float4*)(g_qkv + base) = make_float4(o0,o1,o2,o3);
}

// ---------------- Gram partials + per-slice channel sums ----------------
__global__ __launch_bounds__(256) void k_gram(){
  __shared__ __align__(16) float sh[64*128];
  int b = blockIdx.y, sp = blockIdx.x;
  int tid = threadIdx.x;
  int tc = (tid >> 4) << 2;
  int td = (tid & 15) << 2;
  const float* qb = g_qkv + b*C3*HW + sp*128;
  float4* sh4 = (float4*)sh;
  for (int i = tid; i < 2048; i += 256){
    int c = i >> 5, nn4 = i & 31;
    sh4[c*32 + (nn4 ^ (c>>2))] = *(const float4*)(qb + c*HW + nn4*4);
  }
  __syncthreads();
  u64 acc[4][4];
#pragma unroll
  for (int i = 0; i < 4; i++)
#pragma unroll
    for (int j = 0; j < 4; j++) acc[i][j] = 0ULL;
  const F4U* shf = (const F4U*)sh;
  for (int nn4 = 0; nn4 < 32; nn4++){
    F4U av[4], bv[4];
#pragma unroll
    for (int i = 0; i < 4; i++){ int r = tc + i; av[i] = shf[r*32 + (nn4 ^ (r>>2))]; }
#pragma unroll
    for (int j = 0; j < 4; j++){ int r = td + j; bv[j] = shf[r*32 + (nn4 ^ (r>>2))]; }
#pragma unroll
    for (int i = 0; i < 4; i++)
#pragma unroll
      for (int j = 0; j < 4; j++){
        fma2(acc[i][j], av[i].u.x, bv[j].u.x);
        fma2(acc[i][j], av[i].u.y, bv[j].u.y);
      }
  }
#pragma unroll
  for (int i = 0; i < 4; i++)
#pragma unroll
    for (int j = 0; j < 4; j++)
      g_Gpart[((b*128+sp)*64 + tc+i)*64 + td+j] = hadd2(acc[i][j]);
  if (tid < 64){
    float s = 0.f;
    for (int nn4 = 0; nn4 < 32; nn4++){
      F4U f = shf[tid*32 + (nn4 ^ (tid>>2))];
      s += (f.f.x + f.f.y) + (f.f.z + f.f.w);
    }
    g_Sp[(b*128+sp)*64 + tid] = s;
  }
}

// ---------------- chip-wide reduction: 8 chunks of 16 slices each ----------------
__global__ __launch_bounds__(256) void k_reduce(){
  int t = blockIdx.x*256 + threadIdx.x;      // 131072 threads
  int entry = t & 16383;                     // (b, cd)
  int chunk = t >> 14;                       // 0..7
  int b = entry >> 12, cd = entry & 4095;
  const float* src = g_Gpart + ((size_t)(b*128 + chunk*16))*4096 + cd;
  float s = 0.f;
#pragma unroll
  for (int sp = 0; sp < 16; sp++) s += src[(size_t)sp*4096];
  g_Gred[(size_t)chunk*16384 + entry] = s;
  if (chunk == 0 && cd < 64){
    const float* sq = g_Sp + b*128*64 + cd;
    float ss = 0.f;
#pragma unroll 8
    for (int sp = 0; sp < 128; sp++) ss += sq[sp*64];
    g_S[b*64 + cd] = ss;
  }
}

// ---------------- cov -> sim -> stable ranking ----------------
__global__ void k_stats(){
  __shared__ float covs[64][64];
  __shared__ float stds[64];
  __shared__ float sims[64];
  __shared__ float shS[64];
  int b = blockIdx.x;
  if (threadIdx.x < 64) shS[threadIdx.x] = g_S[b*64 + threadIdx.x];
  __syncthreads();
  for (int pr = threadIdx.x; pr < 4096; pr += 256){
    int c = pr>>6, d = pr&63;
    float g = 0.f;
#pragma unroll
    for (int ch = 0; ch < 8; ch++) g += g_Gred[(size_t)ch*16384 + b*4096 + pr];
    covs[c][d] = g - shS[c]*shS[d]*(1.0f/16384.0f);
  }
  __syncthreads();
  if (threadIdx.x < 64)
    stds[threadIdx.x] = sqrtf(covs[threadIdx.x][threadIdx.x] + 1e-8f);
  __syncthreads();
  if (threadIdx.x < 64){
    int c = threadIdx.x;
    float sc = stds[c], a = 0.f;
    for (int d = 0; d < 64; d++) a += covs[c][d] / fmaxf(sc*stds[d], 1e-8f);
    sims[c] = a * (1.0f/64.0f);
  }
  __syncthreads();
  if (threadIdx.x < 64){
    int c = threadIdx.x;
    float v = sims[c]; int r = 0;
    for (int d = 0; d < 64; d++){
      float u = sims[d];
      r += (u > v) || (u == v && d < c);
    }
    g_idx[b*64 + r] = c;
  }
}

// ---------------- block-local halo attention + gate + scatter ----------------
__global__ __launch_bounds__(64) void k_attn(const float* __restrict__ gatew,
    const float* __restrict__ gateb, const float* __restrict__ temp,
    const float* __restrict__ relh, const float* __restrict__ relw){
  __shared__ int   sc[HD];
  __shared__ __align__(16) float kn[NKEY][HD];
  __shared__ __align__(16) float vv[NKEY][HD];
  __shared__ __align__(16) float gws[HD*HD];
  __shared__ float gbs[HD];
  int tid = threadIdx.x;
  int g = blockIdx.y, b = blockIdx.z;
  if (tid < HD){
    sc[tid]  = g_idx[b*64 + g*HD + tid];
    gbs[tid] = gateb[g*HD + tid];
  }
  for (int i = tid; i < HD*HD; i += 64) gws[i] = gatew[g*HD*HD + i];
  __syncthreads();
  int bh = blockIdx.x >> 4, bw = blockIdx.x & 15;
  int h0 = bh*8, w0 = bw*8;
  for (int p = tid; p < NKEY; p += 64){
    int ry = p/10, rx = p - ry*10;
    int gh = h0 - 1 + ry, gw2 = w0 - 1 + rx;
    bool inb = ((unsigned)gh < 128u) && ((unsigned)gw2 < 128u);
    int posk = gh*128 + gw2;
    float ss = 0.f; float tmp[HD];
#pragma unroll
    for (int c = 0; c < HD; c++){
      float base = 0.f, vval = 0.f;
      if (inb){
        int off = (b*C3 + sc[c])*HW + posk;
        base = g_qkv[off + 64*HW];
        vval = g_qkv[off + 128*HW];
      }
      float rel = (c < 8) ? relh[(g*10+ry)*8 + c] : relw[(g*10+rx)*8 + (c-8)];
      float kv = base + rel;
      tmp[c] = kv; ss += kv*kv;
      vv[p][c] = vval;
    }
    float inv = 1.0f / fmaxf(sqrtf(ss), 1e-12f);
#pragma unroll
    for (int c = 0; c < HD; c++) kn[p][c] = tmp[c]*inv;
  }
  int qy = tid >> 3, qx = tid & 7;
  int pos = (h0+qy)*128 + (w0+qx);
  float qraw[HD]; float ss = 0.f;
#pragma unroll
  for (int c = 0; c < HD; c++){
    float v = g_qkv[(b*C3 + sc[c])*HW + pos];
    qraw[c] = v; ss += v*v;
  }
  u64 qr2[8];
#pragma unroll
  for (int c = 0; c < HD; c += 2) qr2[c>>1] = pack2(qraw[c], qraw[c+1]);
  float E  = __expf(temp[g]);
  float qs = E / fmaxf(sqrtf(ss), 1e-12f);
  __syncthreads();
  float s = 0.f;
  u64 acc2[8];
#pragma unroll
  for (int i = 0; i < 8; i++) acc2[i] = 0ULL;
#pragma unroll 2
  for (int kp = 0; kp < NKEY; kp++){
    const ulonglong2* kk = (const ulonglong2*)kn[kp];
    ulonglong2 k0 = kk[0], k1 = kk[1], k2 = kk[2], k3 = kk[3];
    u64 da = 0ULL, db = 0ULL;
    fma2(da, qr2[0], k0.x); fma2(db, qr2[1], k0.y);
    fma2(da, qr2[2], k1.x); fma2(db, qr2[3], k1.y);
    fma2(da, qr2[4], k2.x); fma2(db, qr2[5], k2.y);
    fma2(da, qr2[6], k3.x); fma2(db, qr2[7], k3.y);
    float l = (hadd2(da) + hadd2(db)) * qs;
    float pv = __expf(l - E);
    s += pv;
    u64 pv2 = pack2(pv, pv);
    const ulonglong2* vk = (const ulonglong2*)vv[kp];
    ulonglong2 v0 = vk[0], v1 = vk[1], v2 = vk[2], v3 = vk[3];
    fma2(acc2[0], pv2, v0.x); fma2(acc2[1], pv2, v0.y);
    fma2(acc2[2], pv2, v1.x); fma2(acc2[3], pv2, v1.y);
    fma2(acc2[4], pv2, v2.x); fma2(acc2[5], pv2, v2.y);
    fma2(acc2[6], pv2, v3.x); fma2(acc2[7], pv2, v3.y);
  }
  float invs = 1.0f / s;
  float accv[HD];
#pragma unroll
  for (int i = 0; i < 8; i++) unpack2(acc2[i], accv[2*i], accv[2*i+1]);
  const ulonglong2* gw2 = (const ulonglong2*)gws;
#pragma unroll
  for (int o = 0; o < HD; o++){
    u64 a = 0ULL;
#pragma unroll
    for (int cc4 = 0; cc4 < 4; cc4++){
      ulonglong2 w = gw2[o*4 + cc4];
      fma2(a, w.x, qr2[2*cc4]); fma2(a, w.y, qr2[2*cc4+1]);
    }
    float ga = gbs[o] + hadd2(a);
    float sig = 1.0f/(1.0f + __expf(-ga));
    g_attn[(b*NCH + sc[o])*HW + pos] = accv[o]*invs*sig;
  }
}

// ---------------- MLP stage A: gate conv + exact gelu * mixed ----------------
__global__ __launch_bounds__(128) void k_mlp_gate(const float* __restrict__ wg_g,
                                                  const float* __restrict__ bg_g){
  __shared__ __align__(16) float wg[4096];
  __shared__ float bg[64];
  for (int i = threadIdx.x; i < 4096; i += 128) wg[i] = wg_g[i];
  if (threadIdx.x < 64) bg[threadIdx.x] = bg_g[threadIdx.x];
  __syncthreads();
  int p = blockIdx.x*128 + threadIdx.x;
  int b = p >> 14, pos = p & 16383;
  const float* ao = g_attn + b*NCH*HW + pos;
  const float* qk = g_qkv  + b*C3*HW + pos;
  u64 mx2[32];
#pragma unroll
  for (int c = 0; c < 64; c += 2){
    float m0 = ao[c*HW]     + qk[c*HW]     + qk[(64+c)*HW];
    float m1 = ao[(c+1)*HW] + qk[(c+1)*HW] + qk[(64+c+1)*HW];
    mx2[c>>1] = pack2(m0, m1);
  }
  float* gout = g_g + b*NCH*HW + pos;
  const ulonglong2* wg2 = (const ulonglong2*)wg;
  for (int o = 0; o < 64; o += 8){
    u64 acc[8];
#pragma unroll
    for (int i = 0; i < 8; i++) acc[i] = 0ULL;
#pragma unroll
    for (int cc4 = 0; cc4 < 16; cc4++){
      u64 x0 = mx2[2*cc4], x1 = mx2[2*cc4+1];
#pragma unroll
      for (int i = 0; i < 8; i++){
        ulonglong2 wv = wg2[(o+i)*16 + cc4];
        fma2(acc[i], wv.x, x0); fma2(acc[i], wv.y, x1);
      }
    }
#pragma unroll
    for (int i = 0; i < 8; i += 2){
      float m0, m1; unpack2(mx2[(o+i)>>1], m0, m1);
      float g0 = bg[o+i]   + hadd2(acc[i]);
      float g1 = bg[o+i+1] + hadd2(acc[i+1]);
      gout[(o+i)*HW]   = 0.5f*g0*(1.0f + erff(g0*0.70710678118f)) * m0;
      gout[(o+i+1)*HW] = 0.5f*g1*(1.0f + erff(g1*0.70710678118f)) * m1;
    }
  }
}

// ---------------- MLP stage B: down -> up(+attn residual) -> proj ----------------
__global__ __launch_bounds__(128) void k_mlp_dup(const float* __restrict__ wd_g,
    const float* __restrict__ bd_g, const float* __restrict__ wu_g,
    const float* __restrict__ bu_g, const float* __restrict__ wp_g){
  __shared__ __align__(16) float wdn[2048];
  __shared__ __align__(16) float wup[2048];
  __shared__ __align__(16) float wpj[4096];
  __shared__ float bdn[32], bup[64];
  for (int i = threadIdx.x; i < 4096; i += 128) wpj[i] = wp_g[i];
  for (int i = threadIdx.x; i < 2048; i += 128){ wdn[i] = wd_g[i]; wup[i] = wu_g[i]; }
  if (threadIdx.x < 32) bdn[threadIdx.x] = bd_g[threadIdx.x];
  if (threadIdx.x < 64) bup[threadIdx.x] = bu_g[threadIdx.x];
  __syncthreads();
  int p = blockIdx.x*128 + threadIdx.x;
  int b = p >> 14, pos = p & 16383;
  const float* gin = g_g + b*NCH*HW + pos;
  u64 g2[32];
#pragma unroll
  for (int c = 0; c < 64; c += 2)
    g2[c>>1] = pack2(gin[c*HW], gin[(c+1)*HW]);
  float dvs[32];
  const ulonglong2* wd2 = (const ulonglong2*)wdn;
  for (int j = 0; j < 32; j += 4){
    u64 a0=0ULL,a1=0ULL,a2_=0ULL,a3=0ULL;
#pragma unroll
    for (int cc4 = 0; cc4 < 16; cc4++){
      u64 x0 = g2[2*cc4], x1 = g2[2*cc4+1];
      ulonglong2 w0 = wd2[(j+0)*16 + cc4];
      ulonglong2 w1 = wd2[(j+1)*16 + cc4];
      ulonglong2 w2 = wd2[(j+2)*16 + cc4];
      ulonglong2 w3 = wd2[(j+3)*16 + cc4];
      fma2(a0, w0.x, x0); fma2(a0, w0.y, x1);
      fma2(a1, w1.x, x0); fma2(a1, w1.y, x1);
      fma2(a2_, w2.x, x0); fma2(a2_, w2.y, x1);
      fma2(a3, w3.x, x0); fma2(a3, w3.y, x1);
    }
    dvs[j+0] = bdn[j+0] + hadd2(a0);
    dvs[j+1] = bdn[j+1] + hadd2(a1);
    dvs[j+2] = bdn[j+2] + hadd2(a2_);
    dvs[j+3] = bdn[j+3] + hadd2(a3);
  }
  u64 dv2[16];
#pragma unroll
  for (int j = 0; j < 32; j += 2) dv2[j>>1] = pack2(dvs[j], dvs[j+1]);
  const float* ao = g_attn + b*NCH*HW + pos;
  u64 o22[32];
  const ulonglong2* wu2 = (const ulonglong2*)wup;
  for (int o = 0; o < 64; o += 8){
    u64 acc[8];
#pragma unroll
    for (int i = 0; i < 8; i++) acc[i] = 0ULL;
#pragma unroll
    for (int jj4 = 0; jj4 < 8; jj4++){
      u64 x0 = dv2[2*jj4], x1 = dv2[2*jj4+1];
#pragma unroll
      for (int i = 0; i < 8; i++){
        ulonglong2 wv = wu2[(o+i)*8 + jj4];
        fma2(acc[i], wv.x, x0); fma2(acc[i], wv.y, x1);
      }
    }
#pragma unroll
    for (int i = 0; i < 8; i += 2)
      o22[(o+i)>>1] = pack2(ao[(o+i)*HW]   + bup[o+i]   + hadd2(acc[i]),
                            ao[(o+i+1)*HW] + bup[o+i+1] + hadd2(acc[i+1]));
  }
  float* outp = g_out3 + b*NCH*HW + pos;
  const ulonglong2* wp2 = (const ulonglong2*)wpj;
  for (int o = 0; o < 64; o += 8){
    u64 acc[8];
#pragma unroll
    for (int i = 0; i < 8; i++) acc[i] = 0ULL;
#pragma unroll
    for (int cc4 = 0; cc4 < 16; cc4++){
      u64 x0 = o22[2*cc4], x1 = o22[2*cc4+1];
#pragma unroll
      for (int i = 0; i < 8; i++){
        ulonglong2 wv = wp2[(o+i)*16 + cc4];
        fma2(acc[i], wv.x, x0); fma2(acc[i], wv.y, x1);
      }
    }
#pragma unroll
    for (int i = 0; i < 8; i++) outp[(o+i)*HW] = hadd2(acc[i]);
  }
}

// ---------------- depthwise 3x3 reflect + bias, 4 px/thread ----------------
__global__ __launch_bounds__(256) void k_lp(const float* __restrict__ wl,
                                            const float* __restrict__ bl){
  int t = blockIdx.x*256 + threadIdx.x;
  int base = t*4;
  int w4 = base & 127, h = (base>>7)&127, bc = base>>14;
  int ch = bc & 63;
  const float* src = g_out3 + bc*HW;
  const float* kk = wl + ch*9;
  float bv = bl[ch];
  float o0=bv,o1=bv,o2=bv,o3=bv;
#pragma unroll
  for (int dy = 0; dy < 3; dy++){
    int ih = h + dy - 1;
    ih = (ih < 0) ? -ih : ((ih > 127) ? 254-ih : ih);
    const float* r = src + ih*128 + w4;
    float4 m = *(const float4*)r;
    float lf = (w4 > 0)   ? r[-1] : r[1];
    float rt = (w4 < 124) ? r[4]  : r[2];
    float ka = kk[dy*3], kb = kk[dy*3+1], kc = kk[dy*3+2];
    o0 = fmaf(lf,ka,fmaf(m.x,kb,fmaf(m.y,kc,o0)));
    o1 = fmaf(m.x,ka,fmaf(m.y,kb,fmaf(m.z,kc,o1)));
    o2 = fmaf(m.y,ka,fmaf(m.z,kb,fmaf(m.w,kc,o2)));
    o3 = fmaf(m.z,ka,fmaf(m.w,kb,fmaf(rt,kc,o3)));
  }
  *(float4*)(g_lp + base) = make_float4(o0,o1,o2,o3);
}

// ---------------- bilinear x2 upsample, align_corners, 4 px/thread float4 ----------------
__global__ __launch_bounds__(256) void k_up(float* __restrict__ outp){
  int t = blockIdx.x*256 + threadIdx.x;
  int ix = t*4;                              // 16777216 outputs
  int X = ix & 255, Y = (ix>>8)&255, bc = ix>>16;
  float cy = Y * (127.0f/255.0f);
  int y0 = (int)cy; if (y0 > 126) y0 = 126;
  float wy = cy - (float)y0;
  const float* tr = g_lp + bc*HW + y0*128;
  float4 res;
#pragma unroll
  for (int i = 0; i < 4; i++){
    float cx = (X+i) * (127.0f/255.0f);
    int x0 = (int)cx; if (x0 > 126) x0 = 126;
    float wx = cx - (float)x0;
    float v00 = tr[x0],       v01 = tr[x0+1];
    float v10 = tr[128+x0],   v11 = tr[128+x0+1];
    float u0 = v00 + (v10 - v00)*wy;
    float u1 = v01 + (v11 - v01)*wy;
    ((float*)&res)[i] = u0 + (u1 - u0)*wx;
  }
  *(float4*)(outp + ix) = res;
}

// ---------------- launch ----------------
extern "C" void kernel_launch(void* const* d_in, const int* in_sizes, int n_in,
                              void* d_out, int out_size){
  const float* x     = (const float*)d_in[0];
  const float* qkvw  = (const float*)d_in[1];
  const float* lcew  = (const float*)d_in[2];
  const float* gatew = (const float*)d_in[3];
  const float* gateb = (const float*)d_in[4];
  const float* temp  = (const float*)d_in[5];
  const float* relh  = (const float*)d_in[6];
  const float* relw  = (const float*)d_in[7];
  const float* downw = (const float*)d_in[8];
  const float* downb = (const float*)d_in[9];
  const float* upw   = (const float*)d_in[10];
  const float* upb   = (const float*)d_in[11];
  const float* gatingw = (const float*)d_in[12];
  const float* gatingb = (const float*)d_in[13];
  const float* projw = (const float*)d_in[14];
  const float* lpw   = (const float*)d_in[15];
  const float* lpb   = (const float*)d_in[16];
  float* outp = (float*)d_out;

  k_pool_qkv<<<512, 128>>>(x, qkvw);
  k_dw3<<<(BATCH*C3*HW)/1024, 256>>>(lcew);
  k_gram<<<dim3(128, BATCH), 256>>>();
  k_reduce<<<512, 256>>>();
  k_stats<<<BATCH, 256>>>();
  k_attn<<<dim3(256, NHEADS, BATCH), 64>>>(gatew, gateb, temp, relh, relw);
  k_mlp_gate<<<512, 128>>>(gatingw, gatingb);
  k_mlp_dup<<<512, 128>>>(downw, downb, upw, upb, projw);
  k_lp<<<(BATCH*NCH*HW)/1024, 256>>>(lpw, lpb);
  k_up<<<(BATCH*NCH*65536)/1024, 256>>>(outp);
}